// round 4
// baseline (speedup 1.0000x reference)
#include <cuda_runtime.h>
#include <math.h>
#include <stdint.h>

// ---------------------------------------------------------------------------
// Problem constants
// ---------------------------------------------------------------------------
#define Bn   8
#define Cc   768
#define Sn   729            // 9*9*9
#define SLD  736            // padded leading dim for scores (16-float aligned)
#define CS   (Cc * Sn)      // 559872
#define NHn  8
#define DH   96             // Cc / NHn
#define BSn  (Bn * Sn)      // 5832 tokens
#define HIDn 2048
#define En   3
#define C3   (3 * Cc)       // 2304
#define EH   (En * HIDn)    // 6144
#define EPSv 1e-5f

// ---------------------------------------------------------------------------
// Scratch (device globals; allocation-free per harness rules)
// ---------------------------------------------------------------------------
__device__ float g_tok   [BSn * Cc];
__device__ float g_qkv   [BSn * C3];
__device__ float g_scores[64 * Sn * SLD];   // padded rows
__device__ float g_attno [BSn * Cc];
__device__ float g_tok2  [BSn * Cc];
__device__ float g_wfull [BSn * En];
__device__ float g_gbuf  [BSn * EH];
__device__ float g_ubuf  [BSn * EH];
__device__ float g_part  [Bn * 64 * 2];
__device__ float g_stats [Bn * 2];

// ---------------------------------------------------------------------------
// tf32 helpers
// ---------------------------------------------------------------------------
__device__ __forceinline__ float tf32_round(float v) {
    uint32_t u;
    asm("cvt.rna.tf32.f32 %0, %1;" : "=r"(u) : "f"(v));
    return __uint_as_float(u);
}

__device__ __forceinline__ void mma_tf32(float* c, const uint32_t* a,
                                         const uint32_t* b) {
    asm volatile(
        "mma.sync.aligned.m16n8k8.row.col.f32.tf32.tf32.f32 "
        "{%0,%1,%2,%3}, {%4,%5,%6,%7}, {%8,%9}, {%0,%1,%2,%3};\n"
        : "+f"(c[0]), "+f"(c[1]), "+f"(c[2]), "+f"(c[3])
        : "r"(a[0]), "r"(a[1]), "r"(a[2]), "r"(a[3]),
          "r"(b[0]), "r"(b[1]));
}

// SMEM layout (floats): A hi/lo [128][36], B hi/lo [32][136]
#define ASTR 36
#define BSTR 136
#define A_ELE (128 * ASTR)
#define B_ELE (32 * BSTR)
#define SMEM_FLOATS (2 * A_ELE + 2 * B_ELE)
#define SMEM_BYTES (SMEM_FLOATS * 4)

// ---------------------------------------------------------------------------
// Generic split-tf32 mma.sync GEMM.
// C = A(MxK) * op(B); BT=false: B is (K x N) row-major; BT=true: B is (N x K)
// row-major (=> C = A * B^T). Tile 128x128, K-chunk 32.
// 3 passes/chunk into the same accumulators: AhiBhi + AhiBlo + AloBhi.
// Batched via blockIdx.z: off = (z/zdiv)*s1 + (z%zdiv)*s2.
// ALIGNMENT REQUIREMENTS (enforced by callers): all of lda/ldb/ldc and all
// batch strides are multiples of 4 floats; bases are 16B-aligned.
// ---------------------------------------------------------------------------
template <bool BT>
__global__ void __launch_bounds__(256)
mma_gemm(const float* __restrict__ A, const float* __restrict__ B,
         float* __restrict__ C,
         int M, int N, int K, int lda, int ldb, int ldc,
         int zdiv,
         long long sA1, long long sA2,
         long long sB1, long long sB2,
         long long sC1, long long sC2) {
    extern __shared__ float smem[];
    float* Ahi = smem;
    float* Alo = Ahi + A_ELE;
    float* Bhi = Alo + A_ELE;
    float* Blo = Bhi + B_ELE;

    int z = blockIdx.z;
    long long zq = z / zdiv, zr = z % zdiv;
    A += zq * sA1 + zr * sA2;
    B += zq * sB1 + zr * sB2;
    C += zq * sC1 + zr * sC2;

    int tid = threadIdx.x, wid = tid >> 5, lane = tid & 31;
    int gid = lane >> 2, tig = lane & 3;
    int m0 = blockIdx.y * 128, n0 = blockIdx.x * 128;
    int wm = (wid & 3) * 32, wn = (wid >> 2) * 64;

    float acc[2][8][4];
    #pragma unroll
    for (int i = 0; i < 2; i++)
        #pragma unroll
        for (int j = 0; j < 8; j++)
            #pragma unroll
            for (int q = 0; q < 4; q++) acc[i][j][q] = 0.f;

    int nchunk = (K + 31) / 32;
    for (int ch = 0; ch < nchunk; ch++) {
        int k0 = ch * 32;

        // ---- A tile [128(M) x 32(K)] -> hi/lo ----
        #pragma unroll
        for (int i = 0; i < 4; i++) {
            int idx = tid + i * 256;          // 1024 float4 slots
            int r = idx >> 3, c4 = idx & 7;
            int gm = m0 + r, gk = k0 + c4 * 4;
            float4 v = make_float4(0.f, 0.f, 0.f, 0.f);
            if (gm < M) {
                if (gk + 3 < K) {
                    v = *(const float4*)(A + (size_t)gm * lda + gk);
                } else {
                    if (gk + 0 < K) v.x = A[(size_t)gm * lda + gk + 0];
                    if (gk + 1 < K) v.y = A[(size_t)gm * lda + gk + 1];
                    if (gk + 2 < K) v.z = A[(size_t)gm * lda + gk + 2];
                    if (gk + 3 < K) v.w = A[(size_t)gm * lda + gk + 3];
                }
            }
            float4 h, l;
            h.x = tf32_round(v.x); l.x = tf32_round(v.x - h.x);
            h.y = tf32_round(v.y); l.y = tf32_round(v.y - h.y);
            h.z = tf32_round(v.z); l.z = tf32_round(v.z - h.z);
            h.w = tf32_round(v.w); l.w = tf32_round(v.w - h.w);
            *(float4*)(Ahi + r * ASTR + c4 * 4) = h;
            *(float4*)(Alo + r * ASTR + c4 * 4) = l;
        }

        // ---- B tile -> Bs[k][n] hi/lo ----
        if (!BT) {
            // B is K x N row-major: direct copy rows
            #pragma unroll
            for (int i = 0; i < 4; i++) {
                int idx = tid + i * 256;
                int kk = idx >> 5, n4 = idx & 31;
                int gk = k0 + kk, gn = n0 + n4 * 4;
                float4 v = make_float4(0.f, 0.f, 0.f, 0.f);
                if (gk < K) {
                    if (gn + 3 < N) {
                        v = *(const float4*)(B + (size_t)gk * ldb + gn);
                    } else {
                        if (gn + 0 < N) v.x = B[(size_t)gk * ldb + gn + 0];
                        if (gn + 1 < N) v.y = B[(size_t)gk * ldb + gn + 1];
                        if (gn + 2 < N) v.z = B[(size_t)gk * ldb + gn + 2];
                        if (gn + 3 < N) v.w = B[(size_t)gk * ldb + gn + 3];
                    }
                }
                float4 h, l;
                h.x = tf32_round(v.x); l.x = tf32_round(v.x - h.x);
                h.y = tf32_round(v.y); l.y = tf32_round(v.y - h.y);
                h.z = tf32_round(v.z); l.z = tf32_round(v.z - h.z);
                h.w = tf32_round(v.w); l.w = tf32_round(v.w - h.w);
                *(float4*)(Bhi + kk * BSTR + n4 * 4) = h;
                *(float4*)(Blo + kk * BSTR + n4 * 4) = l;
            }
        } else {
            // B is N x K row-major: transpose on load (coalesced global reads)
            #pragma unroll
            for (int i = 0; i < 4; i++) {
                int idx = tid + i * 256;
                int r = idx >> 3, c4 = idx & 7;   // r = n row, c4 = k group
                int gn = n0 + r, gk = k0 + c4 * 4;
                float4 v = make_float4(0.f, 0.f, 0.f, 0.f);
                if (gn < N) {
                    if (gk + 3 < K) {
                        v = *(const float4*)(B + (size_t)gn * ldb + gk);
                    } else {
                        if (gk + 0 < K) v.x = B[(size_t)gn * ldb + gk + 0];
                        if (gk + 1 < K) v.y = B[(size_t)gn * ldb + gk + 1];
                        if (gk + 2 < K) v.z = B[(size_t)gn * ldb + gk + 2];
                        if (gk + 3 < K) v.w = B[(size_t)gn * ldb + gk + 3];
                    }
                }
                const float* pv = &v.x;
                #pragma unroll
                for (int j = 0; j < 4; j++) {
                    float val = pv[j];
                    float h = tf32_round(val);
                    float l = tf32_round(val - h);
                    Bhi[(c4 * 4 + j) * BSTR + r] = h;
                    Blo[(c4 * 4 + j) * BSTR + r] = l;
                }
            }
        }

        __syncthreads();

        // ---- 3 split passes of mma ----
        #pragma unroll
        for (int pass = 0; pass < 3; pass++) {
            const uint32_t* Am = (const uint32_t*)((pass == 2) ? Alo : Ahi);
            const uint32_t* Bm = (const uint32_t*)((pass == 1) ? Blo : Bhi);
            #pragma unroll
            for (int ks = 0; ks < 4; ks++) {
                uint32_t a[2][4], b[8][2];
                #pragma unroll
                for (int i = 0; i < 2; i++) {
                    int row = wm + i * 16 + gid;
                    int col = ks * 8 + tig;
                    a[i][0] = Am[row * ASTR + col];
                    a[i][1] = Am[(row + 8) * ASTR + col];
                    a[i][2] = Am[row * ASTR + col + 4];
                    a[i][3] = Am[(row + 8) * ASTR + col + 4];
                }
                #pragma unroll
                for (int j = 0; j < 8; j++) {
                    int kr = ks * 8 + tig;
                    int cn = wn + j * 8 + gid;
                    b[j][0] = Bm[kr * BSTR + cn];
                    b[j][1] = Bm[(kr + 4) * BSTR + cn];
                }
                #pragma unroll
                for (int i = 0; i < 2; i++)
                    #pragma unroll
                    for (int j = 0; j < 8; j++)
                        mma_tf32(acc[i][j], a[i], b[j]);
            }
        }
        __syncthreads();
    }

    // ---- epilogue: fragment stores (float2; ldc and gn are even) ----
    #pragma unroll
    for (int i = 0; i < 2; i++) {
        #pragma unroll
        for (int j = 0; j < 8; j++) {
            int gm0 = m0 + wm + i * 16 + gid;
            int gn = n0 + wn + j * 8 + tig * 2;
            if (gm0 < M) {
                if (gn + 1 < N) {
                    float2 v = make_float2(acc[i][j][0], acc[i][j][1]);
                    *(float2*)(C + (size_t)gm0 * ldc + gn) = v;
                } else if (gn < N) {
                    C[(size_t)gm0 * ldc + gn] = acc[i][j][0];
                }
            }
            int gm1 = gm0 + 8;
            if (gm1 < M) {
                if (gn + 1 < N) {
                    float2 v = make_float2(acc[i][j][2], acc[i][j][3]);
                    *(float2*)(C + (size_t)gm1 * ldc + gn) = v;
                } else if (gn < N) {
                    C[(size_t)gm1 * ldc + gn] = acc[i][j][2];
                }
            }
        }
    }
}

// ---------------------------------------------------------------------------
// LayerNorm: two-stage deterministic reduction + apply-with-transpose
// ---------------------------------------------------------------------------
__global__ void ln_reduce(const float* __restrict__ x) {
    int b = blockIdx.y;
    const float* xb = x + (size_t)b * CS;
    float s = 0.f, sq = 0.f;
    for (int i = blockIdx.x * blockDim.x + threadIdx.x; i < CS;
         i += gridDim.x * blockDim.x) {
        float v = xb[i];
        s += v; sq += v * v;
    }
    __shared__ float sh1[256], sh2[256];
    sh1[threadIdx.x] = s; sh2[threadIdx.x] = sq;
    __syncthreads();
    for (int o = 128; o > 0; o >>= 1) {
        if (threadIdx.x < o) {
            sh1[threadIdx.x] += sh1[threadIdx.x + o];
            sh2[threadIdx.x] += sh2[threadIdx.x + o];
        }
        __syncthreads();
    }
    if (threadIdx.x == 0) {
        g_part[(b * 64 + blockIdx.x) * 2 + 0] = sh1[0];
        g_part[(b * 64 + blockIdx.x) * 2 + 1] = sh2[0];
    }
}

__global__ void ln_finalize() {
    int b = blockIdx.x;
    if (threadIdx.x == 0) {
        float s = 0.f, sq = 0.f;
        for (int i = 0; i < 64; i++) {
            s  += g_part[(b * 64 + i) * 2 + 0];
            sq += g_part[(b * 64 + i) * 2 + 1];
        }
        g_stats[b * 2 + 0] = s;
        g_stats[b * 2 + 1] = sq;
    }
}

__global__ void ln_apply_tr(const float* __restrict__ x,
                            const float* __restrict__ lw,
                            const float* __restrict__ lb) {
    __shared__ float tile[32][33];
    int b = blockIdx.z;
    float mean = g_stats[b * 2 + 0] * (1.f / CS);
    float var  = g_stats[b * 2 + 1] * (1.f / CS) - mean * mean;
    float inv  = rsqrtf(var + EPSv);
    int s0 = blockIdx.x * 32, c0 = blockIdx.y * 32;
    #pragma unroll
    for (int i = 0; i < 4; i++) {
        int cl = threadIdx.y + i * 8;
        int s = s0 + threadIdx.x, c = c0 + cl;
        if (s < Sn && c < Cc) {
            size_t idx = (size_t)c * Sn + s;
            float v = (x[(size_t)b * CS + idx] - mean) * inv * lw[idx] + lb[idx];
            tile[cl][threadIdx.x] = v;
        }
    }
    __syncthreads();
    #pragma unroll
    for (int i = 0; i < 4; i++) {
        int sl = threadIdx.y + i * 8;
        int s = s0 + sl, c = c0 + threadIdx.x;
        if (s < Sn && c < Cc)
            g_tok[((size_t)b * Sn + s) * Cc + c] = tile[threadIdx.x][sl];
    }
}

// ---------------------------------------------------------------------------
// Row softmax (in place, padded leading dim)
// ---------------------------------------------------------------------------
__global__ void softmax_rows(float* __restrict__ data, int n, int ld) {
    float* row = data + (size_t)blockIdx.x * ld;
    __shared__ float sh[256];
    float m = -INFINITY;
    for (int i = threadIdx.x; i < n; i += blockDim.x) m = fmaxf(m, row[i]);
    sh[threadIdx.x] = m; __syncthreads();
    for (int o = 128; o > 0; o >>= 1) {
        if (threadIdx.x < o) sh[threadIdx.x] = fmaxf(sh[threadIdx.x], sh[threadIdx.x + o]);
        __syncthreads();
    }
    m = sh[0]; __syncthreads();
    float sum = 0.f;
    for (int i = threadIdx.x; i < n; i += blockDim.x) {
        float e = expf(row[i] - m);
        row[i] = e; sum += e;
    }
    sh[threadIdx.x] = sum; __syncthreads();
    for (int o = 128; o > 0; o >>= 1) {
        if (threadIdx.x < o) sh[threadIdx.x] += sh[threadIdx.x + o];
        __syncthreads();
    }
    float inv = 1.f / sh[0];
    for (int i = threadIdx.x; i < n; i += blockDim.x) row[i] *= inv;
    // zero the padding so the PV GEMM reads clean zeros
    for (int i = n + threadIdx.x; i < ld; i += blockDim.x) row[i] = 0.f;
}

// ---------------------------------------------------------------------------
// Residual + transpose after proj
// ---------------------------------------------------------------------------
__global__ void addproj_tr(const float* __restrict__ x, float* __restrict__ out) {
    __shared__ float shx[32][33];
    __shared__ float shy[32][33];
    int b = blockIdx.z;
    int s0 = blockIdx.x * 32, c0 = blockIdx.y * 32;
    #pragma unroll
    for (int i = 0; i < 4; i++) {
        int cl = threadIdx.y + i * 8;
        int s = s0 + threadIdx.x, c = c0 + cl;
        if (s < Sn && c < Cc)
            shx[cl][threadIdx.x] = x[(size_t)b * CS + (size_t)c * Sn + s];
    }
    __syncthreads();
    #pragma unroll
    for (int i = 0; i < 4; i++) {
        int sl = threadIdx.y + i * 8;
        int s = s0 + sl, c = c0 + threadIdx.x;
        if (s < Sn && c < Cc) {
            size_t ti = ((size_t)b * Sn + s) * Cc + c;
            float v = shx[threadIdx.x][sl] + g_tok[ti];
            g_tok2[ti] = v;
            shy[threadIdx.x][sl] = v;
        }
    }
    __syncthreads();
    #pragma unroll
    for (int i = 0; i < 4; i++) {
        int cl = threadIdx.y + i * 8;
        int s = s0 + threadIdx.x, c = c0 + cl;
        if (s < Sn && c < Cc)
            out[(size_t)b * CS + (size_t)c * Sn + s] = shy[cl][threadIdx.x];
    }
}

// ---------------------------------------------------------------------------
// Router
// ---------------------------------------------------------------------------
__global__ void router_kernel(const float* __restrict__ rw) {
    int t = blockIdx.x * 8 + (threadIdx.x >> 5);
    int lane = threadIdx.x & 31;
    if (t >= BSn) return;
    const float* tk = g_tok2 + (size_t)t * Cc;
    float s0 = 0.f, s1 = 0.f, s2 = 0.f;
    for (int c = lane; c < Cc; c += 32) {
        float v = tk[c];
        s0 += v * rw[c * 3 + 0];
        s1 += v * rw[c * 3 + 1];
        s2 += v * rw[c * 3 + 2];
    }
    for (int o = 16; o > 0; o >>= 1) {
        s0 += __shfl_down_sync(0xffffffffu, s0, o);
        s1 += __shfl_down_sync(0xffffffffu, s1, o);
        s2 += __shfl_down_sync(0xffffffffu, s2, o);
    }
    if (lane == 0) {
        float m = fmaxf(s0, fmaxf(s1, s2));
        float p0 = expf(s0 - m), p1 = expf(s1 - m), p2 = expf(s2 - m);
        float tot = p0 + p1 + p2;
        p0 /= tot; p1 /= tot; p2 /= tot;
        int amin = 0; float pm = p0;
        if (p1 <= pm) { amin = 1; pm = p1; }
        if (p2 <= pm) { amin = 2; pm = p2; }
        float denom = (p0 + p1 + p2) - pm;
        g_wfull[t * 3 + 0] = (amin == 0) ? 0.f : p0 / denom;
        g_wfull[t * 3 + 1] = (amin == 1) ? 0.f : p1 / denom;
        g_wfull[t * 3 + 2] = (amin == 2) ? 0.f : p2 / denom;
    }
}

// ---------------------------------------------------------------------------
// hid = wfull * silu(g) * u
// ---------------------------------------------------------------------------
__global__ void silu_kernel() {
    size_t n = (size_t)BSn * EH;
    for (size_t i = (size_t)blockIdx.x * blockDim.x + threadIdx.x; i < n;
         i += (size_t)gridDim.x * blockDim.x) {
        float g = g_gbuf[i];
        float u = g_ubuf[i];
        size_t t = i / EH;
        int e = (int)((i % EH) >> 11);
        float w = g_wfull[t * 3 + e];
        float sg = g / (1.f + expf(-g));
        g_gbuf[i] = w * sg * u;
    }
}

// ---------------------------------------------------------------------------
// Final residual with transpose
// ---------------------------------------------------------------------------
__global__ void addmoe_tr(float* __restrict__ out) {
    __shared__ float sh[32][33];
    int b = blockIdx.z;
    int s0 = blockIdx.x * 32, c0 = blockIdx.y * 32;
    #pragma unroll
    for (int i = 0; i < 4; i++) {
        int sl = threadIdx.y + i * 8;
        int s = s0 + sl, c = c0 + threadIdx.x;
        if (s < Sn && c < Cc)
            sh[threadIdx.x][sl] = g_attno[((size_t)b * Sn + s) * Cc + c];
    }
    __syncthreads();
    #pragma unroll
    for (int i = 0; i < 4; i++) {
        int cl = threadIdx.y + i * 8;
        int s = s0 + threadIdx.x, c = c0 + cl;
        if (s < Sn && c < Cc) {
            size_t idx = (size_t)b * CS + (size_t)c * Sn + s;
            out[idx] += sh[cl][threadIdx.x];
        }
    }
}

// ---------------------------------------------------------------------------
// Host launcher
// ---------------------------------------------------------------------------
extern "C" void kernel_launch(void* const* d_in, const int* in_sizes, int n_in,
                              void* d_out, int out_size) {
    const float* x        = (const float*)d_in[0];
    const float* ln_w     = (const float*)d_in[1];
    const float* ln_b     = (const float*)d_in[2];
    const float* qkv_w    = (const float*)d_in[3];
    const float* proj_w   = (const float*)d_in[4];
    const float* router_w = (const float*)d_in[5];
    const float* gate_w   = (const float*)d_in[6];
    const float* up_w     = (const float*)d_in[7];
    const float* down_w   = (const float*)d_in[8];
    float* out = (float*)d_out;

    cudaFuncSetAttribute(mma_gemm<false>, cudaFuncAttributeMaxDynamicSharedMemorySize,
                         SMEM_BYTES);
    cudaFuncSetAttribute(mma_gemm<true>, cudaFuncAttributeMaxDynamicSharedMemorySize,
                         SMEM_BYTES);

    float *tokp, *qkvp, *scoresp, *attnop, *tok2p, *gp, *up;
    cudaGetSymbolAddress((void**)&tokp,    g_tok);
    cudaGetSymbolAddress((void**)&qkvp,    g_qkv);
    cudaGetSymbolAddress((void**)&scoresp, g_scores);
    cudaGetSymbolAddress((void**)&attnop,  g_attno);
    cudaGetSymbolAddress((void**)&tok2p,   g_tok2);
    cudaGetSymbolAddress((void**)&gp,      g_gbuf);
    cudaGetSymbolAddress((void**)&up,      g_ubuf);

    dim3 trGrid((Sn + 31) / 32, Cc / 32, Bn);
    dim3 trBlk(32, 8);

    // 1) LayerNorm
    ln_reduce<<<dim3(64, Bn), 256>>>(x);
    ln_finalize<<<Bn, 1>>>();
    ln_apply_tr<<<trGrid, trBlk>>>(x, ln_w, ln_b);

    // 2) QKV: (5832 x 768) @ (768 x 2304), NN
    mma_gemm<false><<<dim3(18, 46, 1), 256, SMEM_BYTES>>>(
        tokp, qkv_w, qkvp, BSn, C3, Cc, Cc, C3, C3,
        1, 0, 0, 0, 0, 0, 0);

    // 3) scores = Q @ K^T per (b,h): 729x729x96, NT, C ld = SLD (padded)
    mma_gemm<true><<<dim3(6, 6, 64), 256, SMEM_BYTES>>>(
        qkvp, qkvp + Cc, scoresp, Sn, Sn, DH, C3, C3, SLD,
        NHn,
        (long long)Sn * C3, DH,
        (long long)Sn * C3, DH,
        (long long)NHn * Sn * SLD, (long long)Sn * SLD);

    // 4) softmax over rows (length Sn, stride SLD; zeroes padding)
    softmax_rows<<<64 * Sn, 256>>>(scoresp, Sn, SLD);

    // 5) O = P @ V per (b,h): 729x96x729, NN; A ld = SLD
    mma_gemm<false><<<dim3(1, 6, 64), 256, SMEM_BYTES>>>(
        scoresp, qkvp + 2 * Cc, attnop, Sn, DH, Sn, SLD, C3, Cc,
        NHn,
        (long long)NHn * Sn * SLD, (long long)Sn * SLD,
        (long long)Sn * C3, DH,
        (long long)Sn * Cc, DH);

    // 6) proj: (5832 x 768) @ (768 x 768), NN
    mma_gemm<false><<<dim3(6, 46, 1), 256, SMEM_BYTES>>>(
        attnop, proj_w, tokp, BSn, Cc, Cc, Cc, Cc, Cc,
        1, 0, 0, 0, 0, 0, 0);

    // 7) x2 = x + po
    addproj_tr<<<trGrid, trBlk>>>(x, out);

    // 8) router
    router_kernel<<<Sn, 256>>>(router_w);

    // 9) gate/up per expert: (5832 x 768) @ (768 x 2048), NN
    mma_gemm<false><<<dim3(16, 46, En), 256, SMEM_BYTES>>>(
        tok2p, gate_w, gp, BSn, HIDn, Cc, Cc, HIDn, EH,
        1, 0, 0, (long long)Cc * HIDn, 0, HIDn, 0);
    mma_gemm<false><<<dim3(16, 46, En), 256, SMEM_BYTES>>>(
        tok2p, up_w, up, BSn, HIDn, Cc, Cc, HIDn, EH,
        1, 0, 0, (long long)Cc * HIDn, 0, HIDn, 0);

    // 10) hid = wfull * silu(g) * u
    silu_kernel<<<4096, 256>>>();

    // 11) moe = hid (5832 x 6144) @ down_w (6144 x 768), NN
    mma_gemm<false><<<dim3(6, 46, 1), 256, SMEM_BYTES>>>(
        gp, down_w, attnop, BSn, Cc, EH, EH, Cc, Cc,
        1, 0, 0, 0, 0, 0, 0);

    // 12) out += mo
    addmoe_tr<<<trGrid, trBlk>>>(out);

    (void)in_sizes; (void)n_in; (void)out_size;
}

// round 5
// speedup vs baseline: 2.3264x; 2.3264x over previous
#include <cuda_runtime.h>
#include <math.h>
#include <stdint.h>

// ---------------------------------------------------------------------------
// Problem constants
// ---------------------------------------------------------------------------
#define Bn   8
#define Cc   768
#define Sn   729            // 9*9*9
#define SLD  736            // padded leading dim for scores (16-float aligned)
#define CS   (Cc * Sn)      // 559872
#define NHn  8
#define DH   96             // Cc / NHn
#define BSn  (Bn * Sn)      // 5832 tokens
#define HIDn 2048
#define En   3
#define C3   (3 * Cc)       // 2304
#define EH   (En * HIDn)    // 6144
#define EPSv 1e-5f

// ---------------------------------------------------------------------------
// Scratch (device globals; allocation-free per harness rules)
// ---------------------------------------------------------------------------
__device__ float g_tok   [BSn * Cc];
__device__ float g_qkv   [BSn * C3];
__device__ float g_scores[64 * Sn * SLD];
__device__ float g_attno [BSn * Cc];
__device__ float g_tok2  [BSn * Cc];
__device__ float g_wfull [BSn * En];
__device__ float g_gbuf  [BSn * EH];
__device__ float g_ubuf  [BSn * EH];
__device__ float g_part  [Bn * 64 * 2];
__device__ float g_stats [Bn * 2];

// ---------------------------------------------------------------------------
// bf16 split + mma helpers
// ---------------------------------------------------------------------------
// Split two floats into packed bf16 hi (rne) and bf16 lo (of the residual).
__device__ __forceinline__ void split2(float x, float y, uint32_t& hi, uint32_t& lo) {
    uint32_t ux = __float_as_uint(x), uy = __float_as_uint(y);
    uint32_t hx = (ux + 0x7FFFu + ((ux >> 16) & 1u)) & 0xFFFF0000u;
    uint32_t hy = (uy + 0x7FFFu + ((uy >> 16) & 1u)) & 0xFFFF0000u;
    float rx = x - __uint_as_float(hx);
    float ry = y - __uint_as_float(hy);
    hi = (hx >> 16) | hy;
    asm("cvt.rn.bf16x2.f32 %0, %1, %2;" : "=r"(lo) : "f"(ry), "f"(rx));
}

__device__ __forceinline__ void mma_bf16(float* c, const uint32_t* a,
                                         uint32_t b0, uint32_t b1) {
    asm volatile(
        "mma.sync.aligned.m16n8k16.row.col.f32.bf16.bf16.f32 "
        "{%0,%1,%2,%3}, {%4,%5,%6,%7}, {%8,%9}, {%0,%1,%2,%3};\n"
        : "+f"(c[0]), "+f"(c[1]), "+f"(c[2]), "+f"(c[3])
        : "r"(a[0]), "r"(a[1]), "r"(a[2]), "r"(a[3]), "r"(b0), "r"(b1));
}

__device__ __forceinline__ void ldsm_x4(uint32_t* r, uint32_t addr) {
    asm volatile("ldmatrix.sync.aligned.m8n8.x4.shared.b16 {%0,%1,%2,%3}, [%4];"
                 : "=r"(r[0]), "=r"(r[1]), "=r"(r[2]), "=r"(r[3]) : "r"(addr));
}
__device__ __forceinline__ void ldsm_x4_t(uint32_t* r, uint32_t addr) {
    asm volatile("ldmatrix.sync.aligned.m8n8.x4.trans.shared.b16 {%0,%1,%2,%3}, [%4];"
                 : "=r"(r[0]), "=r"(r[1]), "=r"(r[2]), "=r"(r[3]) : "r"(addr));
}

// SMEM (halves): per buffer: Ahi[128*40] Alo[128*40] Bhi Blo (each 5120 halves)
#define ASTRh 40
#define BSTRk 136          // [k][n] layout row stride (BT=false)
#define REGION 5120
#define BUFH  (4 * REGION)
#define SMEM_BYTES (2 * BUFH * 2)

// ---------------------------------------------------------------------------
// Generic bf16x3 mma.sync GEMM (fp32-in / fp32-out, ~2^-18 effective eps).
// C = A(MxK) * op(B); BT=false: B is (K x N) row-major; BT=true: B is (N x K)
// row-major (=> C = A * B^T). Tile 128x128, K-chunk 32, double-buffered,
// register-prefetched. Batched via blockIdx.z: off=(z/zdiv)*s1+(z%zdiv)*s2.
// Alignment: lda/ldb/ldc and batch strides multiples of 4 floats.
// ---------------------------------------------------------------------------
template <bool BT>
__global__ void __launch_bounds__(256)
mma_gemm(const float* __restrict__ A, const float* __restrict__ B,
         float* __restrict__ C,
         int M, int N, int K, int lda, int ldb, int ldc,
         int zdiv,
         long long sA1, long long sA2,
         long long sB1, long long sB2,
         long long sC1, long long sC2) {
    extern __shared__ ushort smem[];
    uint32_t sbase = (uint32_t)__cvta_generic_to_shared(smem);

    int z = blockIdx.z;
    long long zq = z / zdiv, zr = z % zdiv;
    A += zq * sA1 + zr * sA2;
    B += zq * sB1 + zr * sB2;
    C += zq * sC1 + zr * sC2;

    int tid = threadIdx.x, wid = tid >> 5, lane = tid & 31;
    int gid = lane >> 2, tig = lane & 3;
    int m0 = blockIdx.y * 128, n0 = blockIdx.x * 128;
    int wm = (wid & 3) * 32, wn = (wid >> 2) * 64;

    float acc[2][8][4];
    #pragma unroll
    for (int i = 0; i < 2; i++)
        #pragma unroll
        for (int j = 0; j < 8; j++)
            #pragma unroll
            for (int q = 0; q < 4; q++) acc[i][j][q] = 0.f;

    float4 pfa[4], pfb[4];

    auto ldgA = [&](int k0) {
        #pragma unroll
        for (int i = 0; i < 4; i++) {
            int idx = tid + i * 256;
            int r = idx >> 3, c4 = idx & 7;
            int gm = m0 + r, gk = k0 + c4 * 4;
            float4 v = make_float4(0.f, 0.f, 0.f, 0.f);
            if (gm < M) {
                if (gk + 3 < K) {
                    v = *(const float4*)(A + (size_t)gm * lda + gk);
                } else {
                    if (gk + 0 < K) v.x = A[(size_t)gm * lda + gk + 0];
                    if (gk + 1 < K) v.y = A[(size_t)gm * lda + gk + 1];
                    if (gk + 2 < K) v.z = A[(size_t)gm * lda + gk + 2];
                    if (gk + 3 < K) v.w = A[(size_t)gm * lda + gk + 3];
                }
            }
            pfa[i] = v;
        }
    };
    auto ldgB = [&](int k0) {
        #pragma unroll
        for (int i = 0; i < 4; i++) {
            int idx = tid + i * 256;
            float4 v = make_float4(0.f, 0.f, 0.f, 0.f);
            if (!BT) {
                int kk = idx >> 5, n4 = idx & 31;
                int gk = k0 + kk, gn = n0 + n4 * 4;
                if (gk < K) {
                    if (gn + 3 < N) {
                        v = *(const float4*)(B + (size_t)gk * ldb + gn);
                    } else {
                        if (gn + 0 < N) v.x = B[(size_t)gk * ldb + gn + 0];
                        if (gn + 1 < N) v.y = B[(size_t)gk * ldb + gn + 1];
                        if (gn + 2 < N) v.z = B[(size_t)gk * ldb + gn + 2];
                        if (gn + 3 < N) v.w = B[(size_t)gk * ldb + gn + 3];
                    }
                }
            } else {
                int r = idx >> 3, c4 = idx & 7;
                int gn = n0 + r, gk = k0 + c4 * 4;
                if (gn < N) {
                    if (gk + 3 < K) {
                        v = *(const float4*)(B + (size_t)gn * ldb + gk);
                    } else {
                        if (gk + 0 < K) v.x = B[(size_t)gn * ldb + gk + 0];
                        if (gk + 1 < K) v.y = B[(size_t)gn * ldb + gk + 1];
                        if (gk + 2 < K) v.z = B[(size_t)gn * ldb + gk + 2];
                        if (gk + 3 < K) v.w = B[(size_t)gn * ldb + gk + 3];
                    }
                }
            }
            pfb[i] = v;
        }
    };
    auto stsAB = [&](int bufsel) {
        ushort* base = smem + bufsel * BUFH;
        ushort* Ah = base;
        ushort* Al = base + REGION;
        ushort* Bh = base + 2 * REGION;
        ushort* Bl = base + 3 * REGION;
        #pragma unroll
        for (int i = 0; i < 4; i++) {
            int idx = tid + i * 256;
            int r = idx >> 3, c4 = idx & 7;
            float4 v = pfa[i];
            uint32_t h01, l01, h23, l23;
            split2(v.x, v.y, h01, l01);
            split2(v.z, v.w, h23, l23);
            *(uint2*)(Ah + r * ASTRh + c4 * 4) = make_uint2(h01, h23);
            *(uint2*)(Al + r * ASTRh + c4 * 4) = make_uint2(l01, l23);
        }
        #pragma unroll
        for (int i = 0; i < 4; i++) {
            int idx = tid + i * 256;
            float4 v = pfb[i];
            uint32_t h01, l01, h23, l23;
            split2(v.x, v.y, h01, l01);
            split2(v.z, v.w, h23, l23);
            if (!BT) {
                int kk = idx >> 5, n4 = idx & 31;
                *(uint2*)(Bh + kk * BSTRk + n4 * 4) = make_uint2(h01, h23);
                *(uint2*)(Bl + kk * BSTRk + n4 * 4) = make_uint2(l01, l23);
            } else {
                int r = idx >> 3, c4 = idx & 7;
                *(uint2*)(Bh + r * ASTRh + c4 * 4) = make_uint2(h01, h23);
                *(uint2*)(Bl + r * ASTRh + c4 * 4) = make_uint2(l01, l23);
            }
        }
    };

    auto mmaphase = [&](int bufsel) {
        uint32_t base = sbase + bufsel * BUFH * 2;
        uint32_t ah_b = base;
        uint32_t al_b = base + REGION * 2;
        uint32_t bh_b = base + 2 * REGION * 2;
        uint32_t bl_b = base + 3 * REGION * 2;
        #pragma unroll
        for (int ks = 0; ks < 2; ks++) {
            int k16 = ks * 16;
            uint32_t ah[2][4], alr[2][4];
            #pragma unroll
            for (int i = 0; i < 2; i++) {
                int row = wm + i * 16 + (lane & 7) + ((lane & 8) ? 8 : 0);
                int kc = k16 + ((lane & 16) ? 8 : 0);
                uint32_t off = (uint32_t)(row * ASTRh + kc) * 2;
                ldsm_x4(ah[i], ah_b + off);
                ldsm_x4(alr[i], al_b + off);
            }
            #pragma unroll
            for (int jp = 0; jp < 4; jp++) {
                int nj = wn + jp * 16;
                uint32_t bh[4], bl[4];
                if (BT) {
                    int nrow = nj + (lane & 7) + ((lane & 16) ? 8 : 0);
                    int kc = k16 + ((lane & 8) ? 8 : 0);
                    uint32_t off = (uint32_t)(nrow * ASTRh + kc) * 2;
                    ldsm_x4(bh, bh_b + off);
                    ldsm_x4(bl, bl_b + off);
                } else {
                    int krow = k16 + (lane & 7) + ((lane & 8) ? 8 : 0);
                    int ncol = nj + ((lane & 16) ? 8 : 0);
                    uint32_t off = (uint32_t)(krow * BSTRk + ncol) * 2;
                    ldsm_x4_t(bh, bh_b + off);
                    ldsm_x4_t(bl, bl_b + off);
                }
                #pragma unroll
                for (int i = 0; i < 2; i++)
                    #pragma unroll
                    for (int jj = 0; jj < 2; jj++) {
                        float* c = acc[i][jp * 2 + jj];
                        mma_bf16(c, ah[i], bh[2 * jj], bh[2 * jj + 1]);
                        mma_bf16(c, ah[i], bl[2 * jj], bl[2 * jj + 1]);
                        mma_bf16(c, alr[i], bh[2 * jj], bh[2 * jj + 1]);
                    }
            }
        }
    };

    int nchunk = (K + 31) / 32;
    ldgA(0); ldgB(0);
    stsAB(0);
    __syncthreads();
    for (int ch = 0; ch < nchunk; ch++) {
        if (ch + 1 < nchunk) { ldgA((ch + 1) * 32); ldgB((ch + 1) * 32); }
        mmaphase(ch & 1);
        if (ch + 1 < nchunk) stsAB((ch + 1) & 1);
        __syncthreads();
    }

    // ---- epilogue: fragment stores (float2; ldc and gn even) ----
    #pragma unroll
    for (int i = 0; i < 2; i++) {
        #pragma unroll
        for (int j = 0; j < 8; j++) {
            int gm0 = m0 + wm + i * 16 + gid;
            int gn = n0 + wn + j * 8 + tig * 2;
            if (gm0 < M) {
                if (gn + 1 < N) {
                    *(float2*)(C + (size_t)gm0 * ldc + gn) =
                        make_float2(acc[i][j][0], acc[i][j][1]);
                } else if (gn < N) {
                    C[(size_t)gm0 * ldc + gn] = acc[i][j][0];
                }
            }
            int gm1 = gm0 + 8;
            if (gm1 < M) {
                if (gn + 1 < N) {
                    *(float2*)(C + (size_t)gm1 * ldc + gn) =
                        make_float2(acc[i][j][2], acc[i][j][3]);
                } else if (gn < N) {
                    C[(size_t)gm1 * ldc + gn] = acc[i][j][2];
                }
            }
        }
    }
}

// ---------------------------------------------------------------------------
// LayerNorm: two-stage deterministic reduction + apply-with-transpose
// ---------------------------------------------------------------------------
__global__ void ln_reduce(const float* __restrict__ x) {
    int b = blockIdx.y;
    const float* xb = x + (size_t)b * CS;
    float s = 0.f, sq = 0.f;
    for (int i = blockIdx.x * blockDim.x + threadIdx.x; i < CS;
         i += gridDim.x * blockDim.x) {
        float v = xb[i];
        s += v; sq += v * v;
    }
    __shared__ float sh1[256], sh2[256];
    sh1[threadIdx.x] = s; sh2[threadIdx.x] = sq;
    __syncthreads();
    for (int o = 128; o > 0; o >>= 1) {
        if (threadIdx.x < o) {
            sh1[threadIdx.x] += sh1[threadIdx.x + o];
            sh2[threadIdx.x] += sh2[threadIdx.x + o];
        }
        __syncthreads();
    }
    if (threadIdx.x == 0) {
        g_part[(b * 64 + blockIdx.x) * 2 + 0] = sh1[0];
        g_part[(b * 64 + blockIdx.x) * 2 + 1] = sh2[0];
    }
}

__global__ void ln_finalize() {
    int b = blockIdx.x;
    if (threadIdx.x == 0) {
        float s = 0.f, sq = 0.f;
        for (int i = 0; i < 64; i++) {
            s  += g_part[(b * 64 + i) * 2 + 0];
            sq += g_part[(b * 64 + i) * 2 + 1];
        }
        g_stats[b * 2 + 0] = s;
        g_stats[b * 2 + 1] = sq;
    }
}

__global__ void ln_apply_tr(const float* __restrict__ x,
                            const float* __restrict__ lw,
                            const float* __restrict__ lb) {
    __shared__ float tile[32][33];
    int b = blockIdx.z;
    float mean = g_stats[b * 2 + 0] * (1.f / CS);
    float var  = g_stats[b * 2 + 1] * (1.f / CS) - mean * mean;
    float inv  = rsqrtf(var + EPSv);
    int s0 = blockIdx.x * 32, c0 = blockIdx.y * 32;
    #pragma unroll
    for (int i = 0; i < 4; i++) {
        int cl = threadIdx.y + i * 8;
        int s = s0 + threadIdx.x, c = c0 + cl;
        if (s < Sn && c < Cc) {
            size_t idx = (size_t)c * Sn + s;
            float v = (x[(size_t)b * CS + idx] - mean) * inv * lw[idx] + lb[idx];
            tile[cl][threadIdx.x] = v;
        }
    }
    __syncthreads();
    #pragma unroll
    for (int i = 0; i < 4; i++) {
        int sl = threadIdx.y + i * 8;
        int s = s0 + sl, c = c0 + threadIdx.x;
        if (s < Sn && c < Cc)
            g_tok[((size_t)b * Sn + s) * Cc + c] = tile[threadIdx.x][sl];
    }
}

// ---------------------------------------------------------------------------
// Row softmax (in place, padded leading dim)
// ---------------------------------------------------------------------------
__global__ void softmax_rows(float* __restrict__ data, int n, int ld) {
    float* row = data + (size_t)blockIdx.x * ld;
    __shared__ float sh[256];
    float m = -INFINITY;
    for (int i = threadIdx.x; i < n; i += blockDim.x) m = fmaxf(m, row[i]);
    sh[threadIdx.x] = m; __syncthreads();
    for (int o = 128; o > 0; o >>= 1) {
        if (threadIdx.x < o) sh[threadIdx.x] = fmaxf(sh[threadIdx.x], sh[threadIdx.x + o]);
        __syncthreads();
    }
    m = sh[0]; __syncthreads();
    float sum = 0.f;
    for (int i = threadIdx.x; i < n; i += blockDim.x) {
        float e = expf(row[i] - m);
        row[i] = e; sum += e;
    }
    sh[threadIdx.x] = sum; __syncthreads();
    for (int o = 128; o > 0; o >>= 1) {
        if (threadIdx.x < o) sh[threadIdx.x] += sh[threadIdx.x + o];
        __syncthreads();
    }
    float inv = 1.f / sh[0];
    for (int i = threadIdx.x; i < n; i += blockDim.x) row[i] *= inv;
    for (int i = n + threadIdx.x; i < ld; i += blockDim.x) row[i] = 0.f;
}

// ---------------------------------------------------------------------------
// Residual + transpose after proj
// ---------------------------------------------------------------------------
__global__ void addproj_tr(const float* __restrict__ x, float* __restrict__ out) {
    __shared__ float shx[32][33];
    __shared__ float shy[32][33];
    int b = blockIdx.z;
    int s0 = blockIdx.x * 32, c0 = blockIdx.y * 32;
    #pragma unroll
    for (int i = 0; i < 4; i++) {
        int cl = threadIdx.y + i * 8;
        int s = s0 + threadIdx.x, c = c0 + cl;
        if (s < Sn && c < Cc)
            shx[cl][threadIdx.x] = x[(size_t)b * CS + (size_t)c * Sn + s];
    }
    __syncthreads();
    #pragma unroll
    for (int i = 0; i < 4; i++) {
        int sl = threadIdx.y + i * 8;
        int s = s0 + sl, c = c0 + threadIdx.x;
        if (s < Sn && c < Cc) {
            size_t ti = ((size_t)b * Sn + s) * Cc + c;
            float v = shx[threadIdx.x][sl] + g_tok[ti];
            g_tok2[ti] = v;
            shy[threadIdx.x][sl] = v;
        }
    }
    __syncthreads();
    #pragma unroll
    for (int i = 0; i < 4; i++) {
        int cl = threadIdx.y + i * 8;
        int s = s0 + threadIdx.x, c = c0 + cl;
        if (s < Sn && c < Cc)
            out[(size_t)b * CS + (size_t)c * Sn + s] = shy[cl][threadIdx.x];
    }
}

// ---------------------------------------------------------------------------
// Router
// ---------------------------------------------------------------------------
__global__ void router_kernel(const float* __restrict__ rw) {
    int t = blockIdx.x * 8 + (threadIdx.x >> 5);
    int lane = threadIdx.x & 31;
    if (t >= BSn) return;
    const float* tk = g_tok2 + (size_t)t * Cc;
    float s0 = 0.f, s1 = 0.f, s2 = 0.f;
    for (int c = lane; c < Cc; c += 32) {
        float v = tk[c];
        s0 += v * rw[c * 3 + 0];
        s1 += v * rw[c * 3 + 1];
        s2 += v * rw[c * 3 + 2];
    }
    for (int o = 16; o > 0; o >>= 1) {
        s0 += __shfl_down_sync(0xffffffffu, s0, o);
        s1 += __shfl_down_sync(0xffffffffu, s1, o);
        s2 += __shfl_down_sync(0xffffffffu, s2, o);
    }
    if (lane == 0) {
        float m = fmaxf(s0, fmaxf(s1, s2));
        float p0 = expf(s0 - m), p1 = expf(s1 - m), p2 = expf(s2 - m);
        float tot = p0 + p1 + p2;
        p0 /= tot; p1 /= tot; p2 /= tot;
        int amin = 0; float pm = p0;
        if (p1 <= pm) { amin = 1; pm = p1; }
        if (p2 <= pm) { amin = 2; pm = p2; }
        float denom = (p0 + p1 + p2) - pm;
        g_wfull[t * 3 + 0] = (amin == 0) ? 0.f : p0 / denom;
        g_wfull[t * 3 + 1] = (amin == 1) ? 0.f : p1 / denom;
        g_wfull[t * 3 + 2] = (amin == 2) ? 0.f : p2 / denom;
    }
}

// ---------------------------------------------------------------------------
// hid = wfull * silu(g) * u  (vectorized float4)
// ---------------------------------------------------------------------------
__global__ void silu_kernel() {
    size_t n4 = (size_t)BSn * EH / 4;
    for (size_t i = (size_t)blockIdx.x * blockDim.x + threadIdx.x; i < n4;
         i += (size_t)gridDim.x * blockDim.x) {
        float4 g = ((float4*)g_gbuf)[i];
        float4 u = ((float4*)g_ubuf)[i];
        size_t base = i * 4;
        size_t t = base / EH;
        int e = (int)((base % EH) >> 11);
        float w = g_wfull[t * 3 + e];
        float4 r;
        r.x = w * (g.x / (1.f + expf(-g.x))) * u.x;
        r.y = w * (g.y / (1.f + expf(-g.y))) * u.y;
        r.z = w * (g.z / (1.f + expf(-g.z))) * u.z;
        r.w = w * (g.w / (1.f + expf(-g.w))) * u.w;
        ((float4*)g_gbuf)[i] = r;
    }
}

// ---------------------------------------------------------------------------
// Final residual with transpose
// ---------------------------------------------------------------------------
__global__ void addmoe_tr(float* __restrict__ out) {
    __shared__ float sh[32][33];
    int b = blockIdx.z;
    int s0 = blockIdx.x * 32, c0 = blockIdx.y * 32;
    #pragma unroll
    for (int i = 0; i < 4; i++) {
        int sl = threadIdx.y + i * 8;
        int s = s0 + sl, c = c0 + threadIdx.x;
        if (s < Sn && c < Cc)
            sh[threadIdx.x][sl] = g_attno[((size_t)b * Sn + s) * Cc + c];
    }
    __syncthreads();
    #pragma unroll
    for (int i = 0; i < 4; i++) {
        int cl = threadIdx.y + i * 8;
        int s = s0 + threadIdx.x, c = c0 + cl;
        if (s < Sn && c < Cc) {
            size_t idx = (size_t)b * CS + (size_t)c * Sn + s;
            out[idx] += sh[cl][threadIdx.x];
        }
    }
}

// ---------------------------------------------------------------------------
// Host launcher
// ---------------------------------------------------------------------------
extern "C" void kernel_launch(void* const* d_in, const int* in_sizes, int n_in,
                              void* d_out, int out_size) {
    const float* x        = (const float*)d_in[0];
    const float* ln_w     = (const float*)d_in[1];
    const float* ln_b     = (const float*)d_in[2];
    const float* qkv_w    = (const float*)d_in[3];
    const float* proj_w   = (const float*)d_in[4];
    const float* router_w = (const float*)d_in[5];
    const float* gate_w   = (const float*)d_in[6];
    const float* up_w     = (const float*)d_in[7];
    const float* down_w   = (const float*)d_in[8];
    float* out = (float*)d_out;

    cudaFuncSetAttribute(mma_gemm<false>, cudaFuncAttributeMaxDynamicSharedMemorySize,
                         SMEM_BYTES);
    cudaFuncSetAttribute(mma_gemm<true>, cudaFuncAttributeMaxDynamicSharedMemorySize,
                         SMEM_BYTES);

    float *tokp, *qkvp, *scoresp, *attnop, *tok2p, *gp, *up;
    cudaGetSymbolAddress((void**)&tokp,    g_tok);
    cudaGetSymbolAddress((void**)&qkvp,    g_qkv);
    cudaGetSymbolAddress((void**)&scoresp, g_scores);
    cudaGetSymbolAddress((void**)&attnop,  g_attno);
    cudaGetSymbolAddress((void**)&tok2p,   g_tok2);
    cudaGetSymbolAddress((void**)&gp,      g_gbuf);
    cudaGetSymbolAddress((void**)&up,      g_ubuf);

    dim3 trGrid((Sn + 31) / 32, Cc / 32, Bn);
    dim3 trBlk(32, 8);

    // 1) LayerNorm
    ln_reduce<<<dim3(64, Bn), 256>>>(x);
    ln_finalize<<<Bn, 1>>>();
    ln_apply_tr<<<trGrid, trBlk>>>(x, ln_w, ln_b);

    // 2) QKV: (5832 x 768) @ (768 x 2304), NN
    mma_gemm<false><<<dim3(18, 46, 1), 256, SMEM_BYTES>>>(
        tokp, qkv_w, qkvp, BSn, C3, Cc, Cc, C3, C3,
        1, 0, 0, 0, 0, 0, 0);

    // 3) scores = Q @ K^T per (b,h): 729x729x96, NT, C ld = SLD (padded)
    mma_gemm<true><<<dim3(6, 6, 64), 256, SMEM_BYTES>>>(
        qkvp, qkvp + Cc, scoresp, Sn, Sn, DH, C3, C3, SLD,
        NHn,
        (long long)Sn * C3, DH,
        (long long)Sn * C3, DH,
        (long long)NHn * Sn * SLD, (long long)Sn * SLD);

    // 4) softmax (length Sn, stride SLD; zeroes padding)
    softmax_rows<<<64 * Sn, 256>>>(scoresp, Sn, SLD);

    // 5) O = P @ V per (b,h): 729x96x729, NN; A ld = SLD
    mma_gemm<false><<<dim3(1, 6, 64), 256, SMEM_BYTES>>>(
        scoresp, qkvp + 2 * Cc, attnop, Sn, DH, Sn, SLD, C3, Cc,
        NHn,
        (long long)NHn * Sn * SLD, (long long)Sn * SLD,
        (long long)Sn * C3, DH,
        (long long)Sn * Cc, DH);

    // 6) proj: (5832 x 768) @ (768 x 768), NN
    mma_gemm<false><<<dim3(6, 46, 1), 256, SMEM_BYTES>>>(
        attnop, proj_w, tokp, BSn, Cc, Cc, Cc, Cc, Cc,
        1, 0, 0, 0, 0, 0, 0);

    // 7) x2 = x + po
    addproj_tr<<<trGrid, trBlk>>>(x, out);

    // 8) router
    router_kernel<<<Sn, 256>>>(router_w);

    // 9) gate/up per expert: (5832 x 768) @ (768 x 2048), NN
    mma_gemm<false><<<dim3(16, 46, En), 256, SMEM_BYTES>>>(
        tok2p, gate_w, gp, BSn, HIDn, Cc, Cc, HIDn, EH,
        1, 0, 0, (long long)Cc * HIDn, 0, HIDn, 0);
    mma_gemm<false><<<dim3(16, 46, En), 256, SMEM_BYTES>>>(
        tok2p, up_w, up, BSn, HIDn, Cc, Cc, HIDn, EH,
        1, 0, 0, (long long)Cc * HIDn, 0, HIDn, 0);

    // 10) hid = wfull * silu(g) * u
    silu_kernel<<<2048, 256>>>();

    // 11) moe = hid (5832 x 6144) @ down_w (6144 x 768), NN
    mma_gemm<false><<<dim3(6, 46, 1), 256, SMEM_BYTES>>>(
        gp, down_w, attnop, BSn, Cc, EH, EH, Cc, Cc,
        1, 0, 0, 0, 0, 0, 0);

    // 12) out += mo
    addmoe_tr<<<trGrid, trBlk>>>(out);

    (void)in_sizes; (void)n_in; (void)out_size;
}

// round 7
// speedup vs baseline: 2.3982x; 1.0308x over previous
#include <cuda_runtime.h>
#include <math.h>
#include <stdint.h>

// ---------------------------------------------------------------------------
// Problem constants
// ---------------------------------------------------------------------------
#define Bn   8
#define Cc   768
#define Sn   729            // 9*9*9
#define SLD  736            // padded leading dim for scores (16-float aligned; 23*32)
#define CS   (Cc * Sn)      // 559872
#define NHn  8
#define DH   96             // Cc / NHn
#define BSn  (Bn * Sn)      // 5832 tokens
#define HIDn 2048
#define En   3
#define C3   (3 * Cc)       // 2304
#define EH   (En * HIDn)    // 6144
#define EPSv 1e-5f

// ---------------------------------------------------------------------------
// Scratch (device globals; allocation-free per harness rules)
// ---------------------------------------------------------------------------
__device__ float g_tok   [BSn * Cc];
__device__ float g_qkv   [BSn * C3];
__device__ float g_scores[64 * Sn * SLD];
__device__ float g_attno [BSn * Cc];
__device__ float g_tok2  [BSn * Cc];
__device__ float g_wfull [BSn * En];
__device__ float g_gbuf  [BSn * EH];
__device__ float g_ubuf  [BSn * EH];
__device__ float g_part  [Bn * 64 * 2];
__device__ float g_stats [Bn * 2];

// ---------------------------------------------------------------------------
// bf16 split + mma helpers
// ---------------------------------------------------------------------------
__device__ __forceinline__ void split2(float x, float y, uint32_t& hi, uint32_t& lo) {
    uint32_t ux = __float_as_uint(x), uy = __float_as_uint(y);
    uint32_t hx = (ux + 0x7FFFu + ((ux >> 16) & 1u)) & 0xFFFF0000u;
    uint32_t hy = (uy + 0x7FFFu + ((uy >> 16) & 1u)) & 0xFFFF0000u;
    float rx = x - __uint_as_float(hx);
    float ry = y - __uint_as_float(hy);
    hi = (hx >> 16) | hy;
    asm("cvt.rn.bf16x2.f32 %0, %1, %2;" : "=r"(lo) : "f"(ry), "f"(rx));
}

__device__ __forceinline__ void mma_bf16(float* c, const uint32_t* a,
                                         uint32_t b0, uint32_t b1) {
    asm volatile(
        "mma.sync.aligned.m16n8k16.row.col.f32.bf16.bf16.f32 "
        "{%0,%1,%2,%3}, {%4,%5,%6,%7}, {%8,%9}, {%0,%1,%2,%3};\n"
        : "+f"(c[0]), "+f"(c[1]), "+f"(c[2]), "+f"(c[3])
        : "r"(a[0]), "r"(a[1]), "r"(a[2]), "r"(a[3]), "r"(b0), "r"(b1));
}

__device__ __forceinline__ void ldsm_x4(uint32_t* r, uint32_t addr) {
    asm volatile("ldmatrix.sync.aligned.m8n8.x4.shared.b16 {%0,%1,%2,%3}, [%4];"
                 : "=r"(r[0]), "=r"(r[1]), "=r"(r[2]), "=r"(r[3]) : "r"(addr));
}
__device__ __forceinline__ void ldsm_x4_t(uint32_t* r, uint32_t addr) {
    asm volatile("ldmatrix.sync.aligned.m8n8.x4.trans.shared.b16 {%0,%1,%2,%3}, [%4];"
                 : "=r"(r[0]), "=r"(r[1]), "=r"(r[2]), "=r"(r[3]) : "r"(addr));
}

// SMEM (halves): per buffer: Ahi[128*40] Alo[128*40] Bhi Blo (each 5120 halves)
#define ASTRh 40
#define BSTRk 136
#define REGION 5120
#define BUFH  (4 * REGION)
#define SMEM_BYTES (2 * BUFH * 2)

// ---------------------------------------------------------------------------
// Generic bf16x3 mma.sync GEMM (fp32-in / fp32-out).
// ---------------------------------------------------------------------------
template <bool BT>
__global__ void __launch_bounds__(256)
mma_gemm(const float* __restrict__ A, const float* __restrict__ B,
         float* __restrict__ C,
         int M, int N, int K, int lda, int ldb, int ldc,
         int zdiv,
         long long sA1, long long sA2,
         long long sB1, long long sB2,
         long long sC1, long long sC2) {
    extern __shared__ ushort smem[];
    uint32_t sbase = (uint32_t)__cvta_generic_to_shared(smem);

    int z = blockIdx.z;
    long long zq = z / zdiv, zr = z % zdiv;
    A += zq * sA1 + zr * sA2;
    B += zq * sB1 + zr * sB2;
    C += zq * sC1 + zr * sC2;

    int tid = threadIdx.x, wid = tid >> 5, lane = tid & 31;
    int gid = lane >> 2, tig = lane & 3;
    int m0 = blockIdx.y * 128, n0 = blockIdx.x * 128;
    int wm = (wid & 3) * 32, wn = (wid >> 2) * 64;

    // precomputed ldsm per-thread byte offsets (within a buffer region)
    uint32_t aoff[2];
    {
        int arow0 = wm + (lane & 15);
        int akc = (lane & 16) ? 8 : 0;
        aoff[0] = (uint32_t)((arow0)      * ASTRh + akc) * 2;
        aoff[1] = (uint32_t)((arow0 + 16) * ASTRh + akc) * 2;
    }
    uint32_t boff;
    if (BT) {
        int nrow0 = wn + (lane & 7) + ((lane & 16) ? 8 : 0);
        int bkc = (lane & 8) ? 8 : 0;
        boff = (uint32_t)(nrow0 * ASTRh + bkc) * 2;
    } else {
        int krow0 = (lane & 15);
        int ncol0 = wn + ((lane & 16) ? 8 : 0);
        boff = (uint32_t)(krow0 * BSTRk + ncol0) * 2;
    }

    float acc[2][8][4];
    #pragma unroll
    for (int i = 0; i < 2; i++)
        #pragma unroll
        for (int j = 0; j < 8; j++)
            #pragma unroll
            for (int q = 0; q < 4; q++) acc[i][j][q] = 0.f;

    float4 pfa[4], pfb[4];

    auto ldgA = [&](int k0) {
        #pragma unroll
        for (int i = 0; i < 4; i++) {
            int idx = tid + i * 256;
            int r = idx >> 3, c4 = idx & 7;
            int gm = m0 + r, gk = k0 + c4 * 4;
            float4 v = make_float4(0.f, 0.f, 0.f, 0.f);
            if (gm < M) {
                if (gk + 3 < K) {
                    v = *(const float4*)(A + (size_t)gm * lda + gk);
                } else {
                    if (gk + 0 < K) v.x = A[(size_t)gm * lda + gk + 0];
                    if (gk + 1 < K) v.y = A[(size_t)gm * lda + gk + 1];
                    if (gk + 2 < K) v.z = A[(size_t)gm * lda + gk + 2];
                    if (gk + 3 < K) v.w = A[(size_t)gm * lda + gk + 3];
                }
            }
            pfa[i] = v;
        }
    };
    auto ldgB = [&](int k0) {
        #pragma unroll
        for (int i = 0; i < 4; i++) {
            int idx = tid + i * 256;
            float4 v = make_float4(0.f, 0.f, 0.f, 0.f);
            if (!BT) {
                int kk = idx >> 5, n4 = idx & 31;
                int gk = k0 + kk, gn = n0 + n4 * 4;
                if (gk < K) {
                    if (gn + 3 < N) {
                        v = *(const float4*)(B + (size_t)gk * ldb + gn);
                    } else {
                        if (gn + 0 < N) v.x = B[(size_t)gk * ldb + gn + 0];
                        if (gn + 1 < N) v.y = B[(size_t)gk * ldb + gn + 1];
                        if (gn + 2 < N) v.z = B[(size_t)gk * ldb + gn + 2];
                        if (gn + 3 < N) v.w = B[(size_t)gk * ldb + gn + 3];
                    }
                }
            } else {
                int r = idx >> 3, c4 = idx & 7;
                int gn = n0 + r, gk = k0 + c4 * 4;
                if (gn < N) {
                    if (gk + 3 < K) {
                        v = *(const float4*)(B + (size_t)gn * ldb + gk);
                    } else {
                        if (gk + 0 < K) v.x = B[(size_t)gn * ldb + gk + 0];
                        if (gk + 1 < K) v.y = B[(size_t)gn * ldb + gk + 1];
                        if (gk + 2 < K) v.z = B[(size_t)gn * ldb + gk + 2];
                        if (gk + 3 < K) v.w = B[(size_t)gn * ldb + gk + 3];
                    }
                }
            }
            pfb[i] = v;
        }
    };
    auto stsAB = [&](int bufsel) {
        ushort* base = smem + bufsel * BUFH;
        ushort* Ah = base;
        ushort* Al = base + REGION;
        ushort* Bh = base + 2 * REGION;
        ushort* Bl = base + 3 * REGION;
        #pragma unroll
        for (int i = 0; i < 4; i++) {
            int idx = tid + i * 256;
            int r = idx >> 3, c4 = idx & 7;
            float4 v = pfa[i];
            uint32_t h01, l01, h23, l23;
            split2(v.x, v.y, h01, l01);
            split2(v.z, v.w, h23, l23);
            *(uint2*)(Ah + r * ASTRh + c4 * 4) = make_uint2(h01, h23);
            *(uint2*)(Al + r * ASTRh + c4 * 4) = make_uint2(l01, l23);
        }
        #pragma unroll
        for (int i = 0; i < 4; i++) {
            int idx = tid + i * 256;
            float4 v = pfb[i];
            uint32_t h01, l01, h23, l23;
            split2(v.x, v.y, h01, l01);
            split2(v.z, v.w, h23, l23);
            if (!BT) {
                int kk = idx >> 5, n4 = idx & 31;
                *(uint2*)(Bh + kk * BSTRk + n4 * 4) = make_uint2(h01, h23);
                *(uint2*)(Bl + kk * BSTRk + n4 * 4) = make_uint2(l01, l23);
            } else {
                int r = idx >> 3, c4 = idx & 7;
                *(uint2*)(Bh + r * ASTRh + c4 * 4) = make_uint2(h01, h23);
                *(uint2*)(Bl + r * ASTRh + c4 * 4) = make_uint2(l01, l23);
            }
        }
    };

    auto mmaphase = [&](int bufsel) {
        uint32_t base = sbase + bufsel * BUFH * 2;
        uint32_t ah_b = base;
        uint32_t al_b = base + REGION * 2;
        uint32_t bh_b = base + 2 * REGION * 2;
        uint32_t bl_b = base + 3 * REGION * 2;
        #pragma unroll
        for (int ks = 0; ks < 2; ks++) {
            uint32_t ak = (uint32_t)(ks * 16 * 2);
            uint32_t ah[2][4], alr[2][4];
            #pragma unroll
            for (int i = 0; i < 2; i++) {
                ldsm_x4(ah[i], ah_b + aoff[i] + ak);
                ldsm_x4(alr[i], al_b + aoff[i] + ak);
            }
            #pragma unroll
            for (int jp = 0; jp < 4; jp++) {
                uint32_t bh[4], bl[4];
                if (BT) {
                    uint32_t off = boff + (uint32_t)(jp * 16 * ASTRh * 2) + ak;
                    ldsm_x4(bh, bh_b + off);
                    ldsm_x4(bl, bl_b + off);
                } else {
                    uint32_t off = boff + (uint32_t)(ks * 16 * BSTRk * 2) + (uint32_t)(jp * 32);
                    ldsm_x4_t(bh, bh_b + off);
                    ldsm_x4_t(bl, bl_b + off);
                }
                // pass-outer ordering: same-accumulator MMAs are 4 apart
                #pragma unroll
                for (int pass = 0; pass < 3; pass++) {
                    const uint32_t (*af)[4] = (pass == 2) ? alr : ah;
                    const uint32_t* bf = (pass == 1) ? bl : bh;
                    #pragma unroll
                    for (int i = 0; i < 2; i++)
                        #pragma unroll
                        for (int jj = 0; jj < 2; jj++)
                            mma_bf16(acc[i][jp * 2 + jj], af[i],
                                     bf[2 * jj], bf[2 * jj + 1]);
                }
            }
        }
    };

    int nchunk = (K + 31) / 32;
    ldgA(0); ldgB(0);
    stsAB(0);
    __syncthreads();
    for (int ch = 0; ch < nchunk; ch++) {
        if (ch + 1 < nchunk) { ldgA((ch + 1) * 32); ldgB((ch + 1) * 32); }
        mmaphase(ch & 1);
        if (ch + 1 < nchunk) stsAB((ch + 1) & 1);
        __syncthreads();
    }

    // ---- epilogue: fragment stores ----
    #pragma unroll
    for (int i = 0; i < 2; i++) {
        #pragma unroll
        for (int j = 0; j < 8; j++) {
            int gm0 = m0 + wm + i * 16 + gid;
            int gn = n0 + wn + j * 8 + tig * 2;
            if (gm0 < M) {
                if (gn + 1 < N) {
                    *(float2*)(C + (size_t)gm0 * ldc + gn) =
                        make_float2(acc[i][j][0], acc[i][j][1]);
                } else if (gn < N) {
                    C[(size_t)gm0 * ldc + gn] = acc[i][j][0];
                }
            }
            int gm1 = gm0 + 8;
            if (gm1 < M) {
                if (gn + 1 < N) {
                    *(float2*)(C + (size_t)gm1 * ldc + gn) =
                        make_float2(acc[i][j][2], acc[i][j][3]);
                } else if (gn < N) {
                    C[(size_t)gm1 * ldc + gn] = acc[i][j][2];
                }
            }
        }
    }
}

// ---------------------------------------------------------------------------
// LayerNorm
// ---------------------------------------------------------------------------
__global__ void ln_reduce(const float* __restrict__ x) {
    int b = blockIdx.y;
    const float* xb = x + (size_t)b * CS;
    float s = 0.f, sq = 0.f;
    for (int i = blockIdx.x * blockDim.x + threadIdx.x; i < CS;
         i += gridDim.x * blockDim.x) {
        float v = xb[i];
        s += v; sq += v * v;
    }
    __shared__ float sh1[256], sh2[256];
    sh1[threadIdx.x] = s; sh2[threadIdx.x] = sq;
    __syncthreads();
    for (int o = 128; o > 0; o >>= 1) {
        if (threadIdx.x < o) {
            sh1[threadIdx.x] += sh1[threadIdx.x + o];
            sh2[threadIdx.x] += sh2[threadIdx.x + o];
        }
        __syncthreads();
    }
    if (threadIdx.x == 0) {
        g_part[(b * 64 + blockIdx.x) * 2 + 0] = sh1[0];
        g_part[(b * 64 + blockIdx.x) * 2 + 1] = sh2[0];
    }
}

__global__ void ln_finalize() {
    int b = blockIdx.x;
    if (threadIdx.x == 0) {
        float s = 0.f, sq = 0.f;
        for (int i = 0; i < 64; i++) {
            s  += g_part[(b * 64 + i) * 2 + 0];
            sq += g_part[(b * 64 + i) * 2 + 1];
        }
        g_stats[b * 2 + 0] = s;
        g_stats[b * 2 + 1] = sq;
    }
}

__global__ void ln_apply_tr(const float* __restrict__ x,
                            const float* __restrict__ lw,
                            const float* __restrict__ lb) {
    __shared__ float tile[32][33];
    int b = blockIdx.z;
    float mean = g_stats[b * 2 + 0] * (1.f / CS);
    float var  = g_stats[b * 2 + 1] * (1.f / CS) - mean * mean;
    float inv  = rsqrtf(var + EPSv);
    int s0 = blockIdx.x * 32, c0 = blockIdx.y * 32;
    #pragma unroll
    for (int i = 0; i < 4; i++) {
        int cl = threadIdx.y + i * 8;
        int s = s0 + threadIdx.x, c = c0 + cl;
        if (s < Sn && c < Cc) {
            size_t idx = (size_t)c * Sn + s;
            float v = (x[(size_t)b * CS + idx] - mean) * inv * lw[idx] + lb[idx];
            tile[cl][threadIdx.x] = v;
        }
    }
    __syncthreads();
    #pragma unroll
    for (int i = 0; i < 4; i++) {
        int sl = threadIdx.y + i * 8;
        int s = s0 + sl, c = c0 + threadIdx.x;
        if (s < Sn && c < Cc)
            g_tok[((size_t)b * Sn + s) * Cc + c] = tile[threadIdx.x][sl];
    }
}

// ---------------------------------------------------------------------------
// Softmax: ONE WARP PER ROW, register-resident (23*32 = 736 = SLD).
// Single global read + single write; warp-shfl reductions; __expf.
// ---------------------------------------------------------------------------
__global__ void softmax_warp(float* __restrict__ data) {
    int row_id = blockIdx.x * 8 + (threadIdx.x >> 5);
    int lane = threadIdx.x & 31;
    if (row_id >= 64 * Sn) return;
    float* row = data + (size_t)row_id * SLD;
    float v[23];
    float m = -INFINITY;
    #pragma unroll
    for (int i = 0; i < 23; i++) {
        int idx = lane + i * 32;
        v[i] = (idx < Sn) ? row[idx] : -INFINITY;
        m = fmaxf(m, v[i]);
    }
    #pragma unroll
    for (int o = 16; o > 0; o >>= 1)
        m = fmaxf(m, __shfl_xor_sync(0xffffffffu, m, o));
    float sum = 0.f;
    #pragma unroll
    for (int i = 0; i < 23; i++) {
        float e = __expf(v[i] - m);   // __expf(-inf)=0 covers padding lanes
        v[i] = e; sum += e;
    }
    #pragma unroll
    for (int o = 16; o > 0; o >>= 1)
        sum += __shfl_xor_sync(0xffffffffu, sum, o);
    float inv = 1.f / sum;
    #pragma unroll
    for (int i = 0; i < 23; i++)
        row[lane + i * 32] = v[i] * inv;   // padding gets 0
}

// ---------------------------------------------------------------------------
// Residual + transpose after proj
// ---------------------------------------------------------------------------
__global__ void addproj_tr(const float* __restrict__ x, float* __restrict__ out) {
    __shared__ float shx[32][33];
    __shared__ float shy[32][33];
    int b = blockIdx.z;
    int s0 = blockIdx.x * 32, c0 = blockIdx.y * 32;
    #pragma unroll
    for (int i = 0; i < 4; i++) {
        int cl = threadIdx.y + i * 8;
        int s = s0 + threadIdx.x, c = c0 + cl;
        if (s < Sn && c < Cc)
            shx[cl][threadIdx.x] = x[(size_t)b * CS + (size_t)c * Sn + s];
    }
    __syncthreads();
    #pragma unroll
    for (int i = 0; i < 4; i++) {
        int sl = threadIdx.y + i * 8;
        int s = s0 + sl, c = c0 + threadIdx.x;
        if (s < Sn && c < Cc) {
            size_t ti = ((size_t)b * Sn + s) * Cc + c;
            float v = shx[threadIdx.x][sl] + g_tok[ti];
            g_tok2[ti] = v;
            shy[threadIdx.x][sl] = v;
        }
    }
    __syncthreads();
    #pragma unroll
    for (int i = 0; i < 4; i++) {
        int cl = threadIdx.y + i * 8;
        int s = s0 + threadIdx.x, c = c0 + cl;
        if (s < Sn && c < Cc)
            out[(size_t)b * CS + (size_t)c * Sn + s] = shy[cl][threadIdx.x];
    }
}

// ---------------------------------------------------------------------------
// Router
// ---------------------------------------------------------------------------
__global__ void router_kernel(const float* __restrict__ rw) {
    int t = blockIdx.x * 8 + (threadIdx.x >> 5);
    int lane = threadIdx.x & 31;
    if (t >= BSn) return;
    const float* tk = g_tok2 + (size_t)t * Cc;
    float s0 = 0.f, s1 = 0.f, s2 = 0.f;
    for (int c = lane; c < Cc; c += 32) {
        float v = tk[c];
        s0 += v * rw[c * 3 + 0];
        s1 += v * rw[c * 3 + 1];
        s2 += v * rw[c * 3 + 2];
    }
    for (int o = 16; o > 0; o >>= 1) {
        s0 += __shfl_down_sync(0xffffffffu, s0, o);
        s1 += __shfl_down_sync(0xffffffffu, s1, o);
        s2 += __shfl_down_sync(0xffffffffu, s2, o);
    }
    if (lane == 0) {
        float m = fmaxf(s0, fmaxf(s1, s2));
        float p0 = __expf(s0 - m), p1 = __expf(s1 - m), p2 = __expf(s2 - m);
        float tot = p0 + p1 + p2;
        p0 /= tot; p1 /= tot; p2 /= tot;
        int amin = 0; float pm = p0;
        if (p1 <= pm) { amin = 1; pm = p1; }
        if (p2 <= pm) { amin = 2; pm = p2; }
        float denom = (p0 + p1 + p2) - pm;
        g_wfull[t * 3 + 0] = (amin == 0) ? 0.f : p0 / denom;
        g_wfull[t * 3 + 1] = (amin == 1) ? 0.f : p1 / denom;
        g_wfull[t * 3 + 2] = (amin == 2) ? 0.f : p2 / denom;
    }
}

// ---------------------------------------------------------------------------
// hid = wfull * silu(g) * u  (float4, __expf)
// ---------------------------------------------------------------------------
__global__ void silu_kernel() {
    size_t n4 = (size_t)BSn * EH / 4;
    for (size_t i = (size_t)blockIdx.x * blockDim.x + threadIdx.x; i < n4;
         i += (size_t)gridDim.x * blockDim.x) {
        float4 g = ((float4*)g_gbuf)[i];
        float4 u = ((float4*)g_ubuf)[i];
        size_t base = i * 4;
        size_t t = base / EH;
        int e = (int)((base % EH) >> 11);
        float w = g_wfull[t * 3 + e];
        float4 r;
        r.x = w * (g.x / (1.f + __expf(-g.x))) * u.x;
        r.y = w * (g.y / (1.f + __expf(-g.y))) * u.y;
        r.z = w * (g.z / (1.f + __expf(-g.z))) * u.z;
        r.w = w * (g.w / (1.f + __expf(-g.w))) * u.w;
        ((float4*)g_gbuf)[i] = r;
    }
}

// ---------------------------------------------------------------------------
// Final residual with transpose
// ---------------------------------------------------------------------------
__global__ void addmoe_tr(float* __restrict__ out) {
    __shared__ float sh[32][33];
    int b = blockIdx.z;
    int s0 = blockIdx.x * 32, c0 = blockIdx.y * 32;
    #pragma unroll
    for (int i = 0; i < 4; i++) {
        int sl = threadIdx.y + i * 8;
        int s = s0 + sl, c = c0 + threadIdx.x;
        if (s < Sn && c < Cc)
            sh[threadIdx.x][sl] = g_attno[((size_t)b * Sn + s) * Cc + c];
    }
    __syncthreads();
    #pragma unroll
    for (int i = 0; i < 4; i++) {
        int cl = threadIdx.y + i * 8;
        int s = s0 + threadIdx.x, c = c0 + cl;
        if (s < Sn && c < Cc) {
            size_t idx = (size_t)b * CS + (size_t)c * Sn + s;
            out[idx] += sh[cl][threadIdx.x];
        }
    }
}

// ---------------------------------------------------------------------------
// Host launcher
// ---------------------------------------------------------------------------
extern "C" void kernel_launch(void* const* d_in, const int* in_sizes, int n_in,
                              void* d_out, int out_size) {
    const float* x        = (const float*)d_in[0];
    const float* ln_w     = (const float*)d_in[1];
    const float* ln_b     = (const float*)d_in[2];
    const float* qkv_w    = (const float*)d_in[3];
    const float* proj_w   = (const float*)d_in[4];
    const float* router_w = (const float*)d_in[5];
    const float* gate_w   = (const float*)d_in[6];
    const float* up_w     = (const float*)d_in[7];
    const float* down_w   = (const float*)d_in[8];
    float* out = (float*)d_out;

    cudaFuncSetAttribute(mma_gemm<false>, cudaFuncAttributeMaxDynamicSharedMemorySize,
                         SMEM_BYTES);
    cudaFuncSetAttribute(mma_gemm<true>, cudaFuncAttributeMaxDynamicSharedMemorySize,
                         SMEM_BYTES);

    float *tokp, *qkvp, *scoresp, *attnop, *tok2p, *gp, *up;
    cudaGetSymbolAddress((void**)&tokp,    g_tok);
    cudaGetSymbolAddress((void**)&qkvp,    g_qkv);
    cudaGetSymbolAddress((void**)&scoresp, g_scores);
    cudaGetSymbolAddress((void**)&attnop,  g_attno);
    cudaGetSymbolAddress((void**)&tok2p,   g_tok2);
    cudaGetSymbolAddress((void**)&gp,      g_gbuf);
    cudaGetSymbolAddress((void**)&up,      g_ubuf);

    dim3 trGrid((Sn + 31) / 32, Cc / 32, Bn);
    dim3 trBlk(32, 8);

    // 1) LayerNorm
    ln_reduce<<<dim3(64, Bn), 256>>>(x);
    ln_finalize<<<Bn, 1>>>();
    ln_apply_tr<<<trGrid, trBlk>>>(x, ln_w, ln_b);

    // 2) QKV: (5832 x 768) @ (768 x 2304), NN
    mma_gemm<false><<<dim3(18, 46, 1), 256, SMEM_BYTES>>>(
        tokp, qkv_w, qkvp, BSn, C3, Cc, Cc, C3, C3,
        1, 0, 0, 0, 0, 0, 0);

    // 3) scores = Q @ K^T per (b,h): 729x729x96, NT, C ld = SLD
    mma_gemm<true><<<dim3(6, 6, 64), 256, SMEM_BYTES>>>(
        qkvp, qkvp + Cc, scoresp, Sn, Sn, DH, C3, C3, SLD,
        NHn,
        (long long)Sn * C3, DH,
        (long long)Sn * C3, DH,
        (long long)NHn * Sn * SLD, (long long)Sn * SLD);

    // 4) softmax — one warp per row
    softmax_warp<<<64 * Sn / 8, 256>>>(scoresp);

    // 5) O = P @ V per (b,h): 729x96x729, NN; A ld = SLD
    mma_gemm<false><<<dim3(1, 6, 64), 256, SMEM_BYTES>>>(
        scoresp, qkvp + 2 * Cc, attnop, Sn, DH, Sn, SLD, C3, Cc,
        NHn,
        (long long)NHn * Sn * SLD, (long long)Sn * SLD,
        (long long)Sn * C3, DH,
        (long long)Sn * Cc, DH);

    // 6) proj: (5832 x 768) @ (768 x 768), NN
    mma_gemm<false><<<dim3(6, 46, 1), 256, SMEM_BYTES>>>(
        attnop, proj_w, tokp, BSn, Cc, Cc, Cc, Cc, Cc,
        1, 0, 0, 0, 0, 0, 0);

    // 7) x2 = x + po
    addproj_tr<<<trGrid, trBlk>>>(x, out);

    // 8) router
    router_kernel<<<Sn, 256>>>(router_w);

    // 9) gate/up per expert: (5832 x 768) @ (768 x 2048), NN
    mma_gemm<false><<<dim3(16, 46, En), 256, SMEM_BYTES>>>(
        tok2p, gate_w, gp, BSn, HIDn, Cc, Cc, HIDn, EH,
        1, 0, 0, (long long)Cc * HIDn, 0, HIDn, 0);
    mma_gemm<false><<<dim3(16, 46, En), 256, SMEM_BYTES>>>(
        tok2p, up_w, up, BSn, HIDn, Cc, Cc, HIDn, EH,
        1, 0, 0, (long long)Cc * HIDn, 0, HIDn, 0);

    // 10) hid = wfull * silu(g) * u
    silu_kernel<<<2048, 256>>>();

    // 11) moe = hid (5832 x 6144) @ down_w (6144 x 768), NN
    mma_gemm<false><<<dim3(6, 46, 1), 256, SMEM_BYTES>>>(
        gp, down_w, attnop, BSn, Cc, EH, EH, Cc, Cc,
        1, 0, 0, 0, 0, 0, 0);

    // 12) out += mo
    addmoe_tr<<<trGrid, trBlk>>>(out);

    (void)in_sizes; (void)n_in; (void)out_size;
}

// round 8
// speedup vs baseline: 3.8832x; 1.6192x over previous
#include <cuda_runtime.h>
#include <cuda_bf16.h>
#include <math.h>
#include <stdint.h>

// ---------------------------------------------------------------------------
// Problem constants
// ---------------------------------------------------------------------------
#define Bn   8
#define Cc   768
#define Sn   729            // 9*9*9
#define SLD  736            // padded scores leading dim (= 23*32)
#define CS   (Cc * Sn)
#define NHn  8
#define DH   96
#define BSn  (Bn * Sn)      // 5832
#define HIDn 2048
#define En   3
#define C3   (3 * Cc)       // 2304
#define EH   (En * HIDn)    // 6144
#define EPSv 1e-5f

// plane element counts
#define P_TOK   ((long long)BSn * Cc)
#define P_QKV   ((long long)BSn * C3)
#define P_PROB  ((long long)64 * Sn * SLD)
#define P_HID   ((long long)BSn * EH)
#define P_QKVW  ((long long)Cc * C3)
#define P_PROJW ((long long)Cc * Cc)
#define P_GATEW ((long long)En * Cc * HIDn)
#define P_DOWNW ((long long)En * HIDn * Cc)

// ---------------------------------------------------------------------------
// Scratch (device globals)
// ---------------------------------------------------------------------------
__device__ float g_scores[64 * Sn * SLD];
__device__ float g_tok2 [BSn * Cc];
__device__ float g_projo[BSn * Cc];
__device__ float g_gbuf [BSn * EH];
__device__ float g_ubuf [BSn * EH];
__device__ float g_moeo [BSn * Cc];
__device__ float g_wfull[BSn * En];
__device__ float g_part [Bn * 64 * 2];
__device__ float g_stats[Bn * 2];

// split bf16 planes: hi at [0], lo at [P]; +64 pad for benign overreads
__device__ __align__(16) __nv_bfloat16 s_tok  [2 * P_TOK + 64];
__device__ __align__(16) __nv_bfloat16 s_qkv  [2 * P_QKV + 64];
__device__ __align__(16) __nv_bfloat16 s_prob [2 * P_PROB + 64];
__device__ __align__(16) __nv_bfloat16 s_att  [2 * P_TOK + 64];
__device__ __align__(16) __nv_bfloat16 s_tok2 [2 * P_TOK + 64];
__device__ __align__(16) __nv_bfloat16 s_hid  [2 * P_HID + 64];
__device__ __align__(16) __nv_bfloat16 s_qkvw [2 * P_QKVW + 64];
__device__ __align__(16) __nv_bfloat16 s_projw[2 * P_PROJW + 64];
__device__ __align__(16) __nv_bfloat16 s_gatew[2 * P_GATEW + 64];
__device__ __align__(16) __nv_bfloat16 s_upw  [2 * P_GATEW + 64];
__device__ __align__(16) __nv_bfloat16 s_downw[2 * P_DOWNW + 64];

// ---------------------------------------------------------------------------
// split + mma helpers
// ---------------------------------------------------------------------------
__device__ __forceinline__ void split2(float x, float y, uint32_t& hi, uint32_t& lo) {
    uint32_t ux = __float_as_uint(x), uy = __float_as_uint(y);
    uint32_t hx = (ux + 0x7FFFu + ((ux >> 16) & 1u)) & 0xFFFF0000u;
    uint32_t hy = (uy + 0x7FFFu + ((uy >> 16) & 1u)) & 0xFFFF0000u;
    float rx = x - __uint_as_float(hx);
    float ry = y - __uint_as_float(hy);
    hi = (hx >> 16) | hy;
    asm("cvt.rn.bf16x2.f32 %0, %1, %2;" : "=r"(lo) : "f"(ry), "f"(rx));
}

__device__ __forceinline__ void split1(float x, __nv_bfloat16* h, __nv_bfloat16* l) {
    uint32_t ux = __float_as_uint(x);
    uint32_t hx = (ux + 0x7FFFu + ((ux >> 16) & 1u)) & 0xFFFF0000u;
    unsigned short hs = (unsigned short)(hx >> 16);
    *(unsigned short*)h = hs;
    *l = __float2bfloat16(x - __uint_as_float(hx));
}

__device__ __forceinline__ void mma_bf16(float* c, const uint32_t* a,
                                         uint32_t b0, uint32_t b1) {
    asm volatile(
        "mma.sync.aligned.m16n8k16.row.col.f32.bf16.bf16.f32 "
        "{%0,%1,%2,%3}, {%4,%5,%6,%7}, {%8,%9}, {%0,%1,%2,%3};\n"
        : "+f"(c[0]), "+f"(c[1]), "+f"(c[2]), "+f"(c[3])
        : "r"(a[0]), "r"(a[1]), "r"(a[2]), "r"(a[3]), "r"(b0), "r"(b1));
}

__device__ __forceinline__ void ldsm_x4(uint32_t* r, uint32_t addr) {
    asm volatile("ldmatrix.sync.aligned.m8n8.x4.shared.b16 {%0,%1,%2,%3}, [%4];"
                 : "=r"(r[0]), "=r"(r[1]), "=r"(r[2]), "=r"(r[3]) : "r"(addr));
}
__device__ __forceinline__ void ldsm_x4_t(uint32_t* r, uint32_t addr) {
    asm volatile("ldmatrix.sync.aligned.m8n8.x4.trans.shared.b16 {%0,%1,%2,%3}, [%4];"
                 : "=r"(r[0]), "=r"(r[1]), "=r"(r[2]), "=r"(r[3]) : "r"(addr));
}

__device__ __forceinline__ void cpa16(uint32_t dst, const void* src, bool p) {
    int sz = p ? 16 : 0;
    asm volatile("cp.async.cg.shared.global [%0], [%1], 16, %2;"
                 :: "r"(dst), "l"(src), "r"(sz));
}
#define CP_COMMIT() asm volatile("cp.async.commit_group;" ::: "memory")
#define CP_WAIT0()  asm volatile("cp.async.wait_group 0;" ::: "memory")

// SMEM layout (halves): per buffer [Ahi][Alo][Bhi][Blo], each RGN
#define ASTRh 40
#define BSTRk 136
#define RGN   5120
#define BUFH  (4 * RGN)
#define SMEM_BYTES (2 * BUFH * 2)   // 81920

// ---------------------------------------------------------------------------
// bf16x3 mma.sync GEMM on pre-split hi/lo planes; cp.async pipeline.
// A: (M x K) bf16 plane pair (lo at A+asplit), K multiple of 32 reads OK.
// B: BT=false (K x N), BT=true (N x K); lo at B+bsplit; rows >= Kb zero-filled.
// C: OSPLIT ? bf16 plane pair (lo at +csplit) : fp32.
// z batching: off = (z/zdiv)*s1 + (z%zdiv)*s2.
// ---------------------------------------------------------------------------
template <bool BT, bool OSPLIT>
__global__ void __launch_bounds__(256, 2)
mma_gemm(const __nv_bfloat16* __restrict__ A, long long asplit,
         const __nv_bfloat16* __restrict__ B, long long bsplit,
         void* __restrict__ Cv, long long csplit,
         int M, int N, int K, int Kb, int lda, int ldb, int ldc,
         int zdiv,
         long long sA1, long long sA2,
         long long sB1, long long sB2,
         long long sC1, long long sC2) {
    extern __shared__ ushort smem[];
    uint32_t sbase = (uint32_t)__cvta_generic_to_shared(smem);

    int z = blockIdx.z;
    long long zq = z / zdiv, zr = z % zdiv;
    A += zq * sA1 + zr * sA2;
    B += zq * sB1 + zr * sB2;

    int tid = threadIdx.x, wid = tid >> 5, lane = tid & 31;
    int gid = lane >> 2, tig = lane & 3;
    int m0 = blockIdx.y * 128, n0 = blockIdx.x * 128;
    int wm = (wid & 3) * 32, wn = (wid >> 2) * 64;

    // ldsm byte offsets within a buffer region
    uint32_t aoff[2];
    {
        int arow0 = wm + (lane & 15);
        int akc = (lane & 16) ? 8 : 0;
        aoff[0] = (uint32_t)((arow0)      * ASTRh + akc) * 2;
        aoff[1] = (uint32_t)((arow0 + 16) * ASTRh + akc) * 2;
    }
    uint32_t boff;
    if (BT) {
        int nrow0 = wn + (lane & 7) + ((lane & 16) ? 8 : 0);
        int bkc = (lane & 8) ? 8 : 0;
        boff = (uint32_t)(nrow0 * ASTRh + bkc) * 2;
    } else {
        int krow0 = (lane & 15);
        int ncol0 = wn + ((lane & 16) ? 8 : 0);
        boff = (uint32_t)(krow0 * BSTRk + ncol0) * 2;
    }

    float acc[2][8][4];
    #pragma unroll
    for (int i = 0; i < 2; i++)
        #pragma unroll
        for (int j = 0; j < 8; j++)
            #pragma unroll
            for (int q = 0; q < 4; q++) acc[i][j][q] = 0.f;

    auto cp_chunk = [&](int k0, int buf) {
        uint32_t bb = sbase + (uint32_t)buf * BUFH * 2;
        // A tile: 128 rows x 32 halves; 4 x 16B segs/row
        #pragma unroll
        for (int p = 0; p < 2; p++) {
            int r = (tid >> 2) + p * 64;
            int seg = tid & 3;
            int gm = m0 + r;
            const __nv_bfloat16* src = A + (size_t)gm * lda + k0 + seg * 8;
            uint32_t d = bb + (uint32_t)(r * ASTRh + seg * 8) * 2;
            bool pr = (gm < M);
            cpa16(d, src, pr);
            cpa16(d + RGN * 2, src + asplit, pr);
        }
        if (BT) {
            #pragma unroll
            for (int p = 0; p < 2; p++) {
                int r = (tid >> 2) + p * 64;
                int seg = tid & 3;
                int gn = n0 + r;
                const __nv_bfloat16* src = B + (size_t)gn * ldb + k0 + seg * 8;
                uint32_t d = bb + (uint32_t)(2 * RGN * 2)
                           + (uint32_t)(r * ASTRh + seg * 8) * 2;
                bool pr = (gn < N);
                cpa16(d, src, pr);
                cpa16(d + RGN * 2, src + bsplit, pr);
            }
        } else {
            // B tile: 32 k-rows x 128 halves; 16 x 16B segs/row
            #pragma unroll
            for (int p = 0; p < 2; p++) {
                int kr = (tid >> 4) + p * 16;
                int seg = tid & 15;
                int gk = k0 + kr;
                const __nv_bfloat16* src = B + (size_t)gk * ldb + n0 + seg * 8;
                uint32_t d = bb + (uint32_t)(2 * RGN * 2)
                           + (uint32_t)(kr * BSTRk + seg * 8) * 2;
                bool pr = (gk < Kb);
                cpa16(d, src, pr);
                cpa16(d + RGN * 2, src + bsplit, pr);
            }
        }
    };

    auto mmaphase = [&](int bufsel) {
        uint32_t base = sbase + (uint32_t)bufsel * BUFH * 2;
        uint32_t ah_b = base;
        uint32_t al_b = base + RGN * 2;
        uint32_t bh_b = base + 2 * RGN * 2;
        uint32_t bl_b = base + 3 * RGN * 2;
        #pragma unroll
        for (int ks = 0; ks < 2; ks++) {
            uint32_t ak = (uint32_t)(ks * 16 * 2);
            uint32_t ah[2][4], alr[2][4];
            #pragma unroll
            for (int i = 0; i < 2; i++) {
                ldsm_x4(ah[i], ah_b + aoff[i] + ak);
                ldsm_x4(alr[i], al_b + aoff[i] + ak);
            }
            #pragma unroll
            for (int jp = 0; jp < 4; jp++) {
                uint32_t bh[4], bl[4];
                if (BT) {
                    uint32_t off = boff + (uint32_t)(jp * 16 * ASTRh * 2) + ak;
                    ldsm_x4(bh, bh_b + off);
                    ldsm_x4(bl, bl_b + off);
                } else {
                    uint32_t off = boff + (uint32_t)(ks * 16 * BSTRk * 2)
                                 + (uint32_t)(jp * 32);
                    ldsm_x4_t(bh, bh_b + off);
                    ldsm_x4_t(bl, bl_b + off);
                }
                #pragma unroll
                for (int pass = 0; pass < 3; pass++) {
                    const uint32_t (*af)[4] = (pass == 2) ? alr : ah;
                    const uint32_t* bf = (pass == 1) ? bl : bh;
                    #pragma unroll
                    for (int i = 0; i < 2; i++)
                        #pragma unroll
                        for (int jj = 0; jj < 2; jj++)
                            mma_bf16(acc[i][jp * 2 + jj], af[i],
                                     bf[2 * jj], bf[2 * jj + 1]);
                }
            }
        }
    };

    int nchunk = K >> 5;   // callers guarantee K % 32 == 0
    cp_chunk(0, 0); CP_COMMIT();
    for (int ch = 0; ch < nchunk; ch++) {
        CP_WAIT0();
        __syncthreads();
        if (ch + 1 < nchunk) { cp_chunk((ch + 1) * 32, (ch + 1) & 1); CP_COMMIT(); }
        mmaphase(ch & 1);
    }

    // ---- epilogue ----
    if (OSPLIT) {
        __nv_bfloat16* Ch = (__nv_bfloat16*)Cv + zq * sC1 + zr * sC2;
        #pragma unroll
        for (int i = 0; i < 2; i++) {
            #pragma unroll
            for (int j = 0; j < 8; j++) {
                int gm0 = m0 + wm + i * 16 + gid;
                int gn = n0 + wn + j * 8 + tig * 2;
                if (gm0 < M && gn + 1 < N) {
                    uint32_t h, l;
                    split2(acc[i][j][0], acc[i][j][1], h, l);
                    *(uint32_t*)(Ch + (size_t)gm0 * ldc + gn) = h;
                    *(uint32_t*)(Ch + csplit + (size_t)gm0 * ldc + gn) = l;
                }
                int gm1 = gm0 + 8;
                if (gm1 < M && gn + 1 < N) {
                    uint32_t h, l;
                    split2(acc[i][j][2], acc[i][j][3], h, l);
                    *(uint32_t*)(Ch + (size_t)gm1 * ldc + gn) = h;
                    *(uint32_t*)(Ch + csplit + (size_t)gm1 * ldc + gn) = l;
                }
            }
        }
    } else {
        float* C = (float*)Cv + zq * sC1 + zr * sC2;
        #pragma unroll
        for (int i = 0; i < 2; i++) {
            #pragma unroll
            for (int j = 0; j < 8; j++) {
                int gm0 = m0 + wm + i * 16 + gid;
                int gn = n0 + wn + j * 8 + tig * 2;
                if (gm0 < M) {
                    if (gn + 1 < N) {
                        *(float2*)(C + (size_t)gm0 * ldc + gn) =
                            make_float2(acc[i][j][0], acc[i][j][1]);
                    } else if (gn < N) {
                        C[(size_t)gm0 * ldc + gn] = acc[i][j][0];
                    }
                }
                int gm1 = gm0 + 8;
                if (gm1 < M) {
                    if (gn + 1 < N) {
                        *(float2*)(C + (size_t)gm1 * ldc + gn) =
                            make_float2(acc[i][j][2], acc[i][j][3]);
                    } else if (gn < N) {
                        C[(size_t)gm1 * ldc + gn] = acc[i][j][2];
                    }
                }
            }
        }
    }
}

// ---------------------------------------------------------------------------
// fp32 -> split bf16 planes (for weights)
// ---------------------------------------------------------------------------
__global__ void convert_split(const float* __restrict__ src,
                              __nv_bfloat16* __restrict__ dst,
                              long long psplit, long long n4) {
    for (long long i = (long long)blockIdx.x * blockDim.x + threadIdx.x; i < n4;
         i += (long long)gridDim.x * blockDim.x) {
        float4 v = ((const float4*)src)[i];
        uint32_t h01, l01, h23, l23;
        split2(v.x, v.y, h01, l01);
        split2(v.z, v.w, h23, l23);
        ((uint2*)dst)[i] = make_uint2(h01, h23);
        ((uint2*)(dst + psplit))[i] = make_uint2(l01, l23);
    }
}

// ---------------------------------------------------------------------------
// LayerNorm
// ---------------------------------------------------------------------------
__global__ void ln_reduce(const float* __restrict__ x) {
    int b = blockIdx.y;
    const float* xb = x + (size_t)b * CS;
    float s = 0.f, sq = 0.f;
    for (int i = blockIdx.x * blockDim.x + threadIdx.x; i < CS;
         i += gridDim.x * blockDim.x) {
        float v = xb[i];
        s += v; sq += v * v;
    }
    __shared__ float sh1[256], sh2[256];
    sh1[threadIdx.x] = s; sh2[threadIdx.x] = sq;
    __syncthreads();
    for (int o = 128; o > 0; o >>= 1) {
        if (threadIdx.x < o) {
            sh1[threadIdx.x] += sh1[threadIdx.x + o];
            sh2[threadIdx.x] += sh2[threadIdx.x + o];
        }
        __syncthreads();
    }
    if (threadIdx.x == 0) {
        g_part[(b * 64 + blockIdx.x) * 2 + 0] = sh1[0];
        g_part[(b * 64 + blockIdx.x) * 2 + 1] = sh2[0];
    }
}

__global__ void ln_finalize() {
    int b = blockIdx.x, t = threadIdx.x;   // 64 threads
    float s = g_part[(b * 64 + t) * 2 + 0];
    float sq = g_part[(b * 64 + t) * 2 + 1];
    for (int o = 16; o > 0; o >>= 1) {
        s  += __shfl_down_sync(0xffffffffu, s, o);
        sq += __shfl_down_sync(0xffffffffu, sq, o);
    }
    __shared__ float a0[2], a1[2];
    if ((t & 31) == 0) { a0[t >> 5] = s; a1[t >> 5] = sq; }
    __syncthreads();
    if (t == 0) {
        g_stats[b * 2 + 0] = a0[0] + a0[1];
        g_stats[b * 2 + 1] = a1[0] + a1[1];
    }
}

// apply LN, transpose, write split tok planes
__global__ void ln_apply_tr(const float* __restrict__ x,
                            const float* __restrict__ lw,
                            const float* __restrict__ lb) {
    __shared__ float tile[32][33];
    int b = blockIdx.z;
    float mean = g_stats[b * 2 + 0] * (1.f / CS);
    float var  = g_stats[b * 2 + 1] * (1.f / CS) - mean * mean;
    float inv  = rsqrtf(var + EPSv);
    int s0 = blockIdx.x * 32, c0 = blockIdx.y * 32;
    #pragma unroll
    for (int i = 0; i < 4; i++) {
        int cl = threadIdx.y + i * 8;
        int s = s0 + threadIdx.x, c = c0 + cl;
        if (s < Sn && c < Cc) {
            size_t idx = (size_t)c * Sn + s;
            float v = (x[(size_t)b * CS + idx] - mean) * inv * lw[idx] + lb[idx];
            tile[cl][threadIdx.x] = v;
        }
    }
    __syncthreads();
    #pragma unroll
    for (int i = 0; i < 4; i++) {
        int sl = threadIdx.y + i * 8;
        int s = s0 + sl, c = c0 + threadIdx.x;
        if (s < Sn && c < Cc) {
            size_t ti = ((size_t)b * Sn + s) * Cc + c;
            split1(tile[threadIdx.x][sl], &s_tok[ti], &s_tok[P_TOK + ti]);
        }
    }
}

// ---------------------------------------------------------------------------
// Softmax: one warp per row; reads fp32 scores, writes split prob planes.
// ---------------------------------------------------------------------------
__global__ void softmax_warp(const float* __restrict__ data) {
    int row_id = blockIdx.x * 8 + (threadIdx.x >> 5);
    int lane = threadIdx.x & 31;
    if (row_id >= 64 * Sn) return;
    const float* row = data + (size_t)row_id * SLD;
    float v[23];
    float m = -INFINITY;
    #pragma unroll
    for (int i = 0; i < 23; i++) {
        int idx = lane + i * 32;
        v[i] = (idx < Sn) ? row[idx] : -INFINITY;
        m = fmaxf(m, v[i]);
    }
    #pragma unroll
    for (int o = 16; o > 0; o >>= 1)
        m = fmaxf(m, __shfl_xor_sync(0xffffffffu, m, o));
    float sum = 0.f;
    #pragma unroll
    for (int i = 0; i < 23; i++) {
        float e = __expf(v[i] - m);
        v[i] = e; sum += e;
    }
    #pragma unroll
    for (int o = 16; o > 0; o >>= 1)
        sum += __shfl_xor_sync(0xffffffffu, sum, o);
    float inv = 1.f / sum;
    size_t base = (size_t)row_id * SLD + lane;
    #pragma unroll
    for (int i = 0; i < 23; i++) {
        size_t ti = base + i * 32;
        split1(v[i] * inv, &s_prob[ti], &s_prob[P_PROB + ti]);
    }
}

// ---------------------------------------------------------------------------
// x2 = x + proj_out: write out (b,c,s), g_tok2 fp32, s_tok2 planes
// ---------------------------------------------------------------------------
__global__ void addproj_tr(const float* __restrict__ x, float* __restrict__ out) {
    __shared__ float shx[32][33];
    __shared__ float shy[32][33];
    int b = blockIdx.z;
    int s0 = blockIdx.x * 32, c0 = blockIdx.y * 32;
    #pragma unroll
    for (int i = 0; i < 4; i++) {
        int cl = threadIdx.y + i * 8;
        int s = s0 + threadIdx.x, c = c0 + cl;
        if (s < Sn && c < Cc)
            shx[cl][threadIdx.x] = x[(size_t)b * CS + (size_t)c * Sn + s];
    }
    __syncthreads();
    #pragma unroll
    for (int i = 0; i < 4; i++) {
        int sl = threadIdx.y + i * 8;
        int s = s0 + sl, c = c0 + threadIdx.x;
        if (s < Sn && c < Cc) {
            size_t ti = ((size_t)b * Sn + s) * Cc + c;
            float v = shx[threadIdx.x][sl] + g_projo[ti];
            g_tok2[ti] = v;
            split1(v, &s_tok2[ti], &s_tok2[P_TOK + ti]);
            shy[threadIdx.x][sl] = v;
        }
    }
    __syncthreads();
    #pragma unroll
    for (int i = 0; i < 4; i++) {
        int cl = threadIdx.y + i * 8;
        int s = s0 + threadIdx.x, c = c0 + cl;
        if (s < Sn && c < Cc)
            out[(size_t)b * CS + (size_t)c * Sn + s] = shy[cl][threadIdx.x];
    }
}

// ---------------------------------------------------------------------------
// Router
// ---------------------------------------------------------------------------
__global__ void router_kernel(const float* __restrict__ rw) {
    int t = blockIdx.x * 8 + (threadIdx.x >> 5);
    int lane = threadIdx.x & 31;
    if (t >= BSn) return;
    const float* tk = g_tok2 + (size_t)t * Cc;
    float s0 = 0.f, s1 = 0.f, s2 = 0.f;
    for (int c = lane; c < Cc; c += 32) {
        float v = tk[c];
        s0 += v * rw[c * 3 + 0];
        s1 += v * rw[c * 3 + 1];
        s2 += v * rw[c * 3 + 2];
    }
    for (int o = 16; o > 0; o >>= 1) {
        s0 += __shfl_down_sync(0xffffffffu, s0, o);
        s1 += __shfl_down_sync(0xffffffffu, s1, o);
        s2 += __shfl_down_sync(0xffffffffu, s2, o);
    }
    if (lane == 0) {
        float m = fmaxf(s0, fmaxf(s1, s2));
        float p0 = __expf(s0 - m), p1 = __expf(s1 - m), p2 = __expf(s2 - m);
        float tot = p0 + p1 + p2;
        p0 /= tot; p1 /= tot; p2 /= tot;
        int amin = 0; float pm = p0;
        if (p1 <= pm) { amin = 1; pm = p1; }
        if (p2 <= pm) { amin = 2; pm = p2; }
        float denom = (p0 + p1 + p2) - pm;
        g_wfull[t * 3 + 0] = (amin == 0) ? 0.f : p0 / denom;
        g_wfull[t * 3 + 1] = (amin == 1) ? 0.f : p1 / denom;
        g_wfull[t * 3 + 2] = (amin == 2) ? 0.f : p2 / denom;
    }
}

// ---------------------------------------------------------------------------
// hid = wfull * silu(g) * u -> split planes
// ---------------------------------------------------------------------------
__global__ void silu_kernel() {
    size_t n4 = (size_t)BSn * EH / 4;
    for (size_t i = (size_t)blockIdx.x * blockDim.x + threadIdx.x; i < n4;
         i += (size_t)gridDim.x * blockDim.x) {
        float4 g = ((float4*)g_gbuf)[i];
        float4 u = ((float4*)g_ubuf)[i];
        size_t base = i * 4;
        size_t t = base / EH;
        int e = (int)((base % EH) >> 11);
        float w = g_wfull[t * 3 + e];
        float4 r;
        r.x = w * (g.x / (1.f + __expf(-g.x))) * u.x;
        r.y = w * (g.y / (1.f + __expf(-g.y))) * u.y;
        r.z = w * (g.z / (1.f + __expf(-g.z))) * u.z;
        r.w = w * (g.w / (1.f + __expf(-g.w))) * u.w;
        uint32_t h01, l01, h23, l23;
        split2(r.x, r.y, h01, l01);
        split2(r.z, r.w, h23, l23);
        ((uint2*)s_hid)[i] = make_uint2(h01, h23);
        ((uint2*)(s_hid + P_HID))[i] = make_uint2(l01, l23);
    }
}

// ---------------------------------------------------------------------------
// out += moe_out (transposed)
// ---------------------------------------------------------------------------
__global__ void addmoe_tr(float* __restrict__ out) {
    __shared__ float sh[32][33];
    int b = blockIdx.z;
    int s0 = blockIdx.x * 32, c0 = blockIdx.y * 32;
    #pragma unroll
    for (int i = 0; i < 4; i++) {
        int sl = threadIdx.y + i * 8;
        int s = s0 + sl, c = c0 + threadIdx.x;
        if (s < Sn && c < Cc)
            sh[threadIdx.x][sl] = g_moeo[((size_t)b * Sn + s) * Cc + c];
    }
    __syncthreads();
    #pragma unroll
    for (int i = 0; i < 4; i++) {
        int cl = threadIdx.y + i * 8;
        int s = s0 + threadIdx.x, c = c0 + cl;
        if (s < Sn && c < Cc) {
            size_t idx = (size_t)b * CS + (size_t)c * Sn + s;
            out[idx] += sh[cl][threadIdx.x];
        }
    }
}

// ---------------------------------------------------------------------------
// Host launcher
// ---------------------------------------------------------------------------
extern "C" void kernel_launch(void* const* d_in, const int* in_sizes, int n_in,
                              void* d_out, int out_size) {
    const float* x        = (const float*)d_in[0];
    const float* ln_w     = (const float*)d_in[1];
    const float* ln_b     = (const float*)d_in[2];
    const float* qkv_w    = (const float*)d_in[3];
    const float* proj_w   = (const float*)d_in[4];
    const float* router_w = (const float*)d_in[5];
    const float* gate_w   = (const float*)d_in[6];
    const float* up_w     = (const float*)d_in[7];
    const float* down_w   = (const float*)d_in[8];
    float* out = (float*)d_out;

    cudaFuncSetAttribute(mma_gemm<false, false>,
                         cudaFuncAttributeMaxDynamicSharedMemorySize, SMEM_BYTES);
    cudaFuncSetAttribute(mma_gemm<false, true>,
                         cudaFuncAttributeMaxDynamicSharedMemorySize, SMEM_BYTES);
    cudaFuncSetAttribute(mma_gemm<true, false>,
                         cudaFuncAttributeMaxDynamicSharedMemorySize, SMEM_BYTES);

    float *scoresp, *projop, *gp, *up, *moeop;
    __nv_bfloat16 *tokp, *qkvp, *probp, *attp, *tok2p;
    __nv_bfloat16 *qkvwp, *projwp, *gatewp, *upwp, *downwp;
    cudaGetSymbolAddress((void**)&scoresp, g_scores);
    cudaGetSymbolAddress((void**)&projop,  g_projo);
    cudaGetSymbolAddress((void**)&gp,      g_gbuf);
    cudaGetSymbolAddress((void**)&up,      g_ubuf);
    cudaGetSymbolAddress((void**)&moeop,   g_moeo);
    cudaGetSymbolAddress((void**)&tokp,    s_tok);
    cudaGetSymbolAddress((void**)&qkvp,    s_qkv);
    cudaGetSymbolAddress((void**)&probp,   s_prob);
    cudaGetSymbolAddress((void**)&attp,    s_att);
    cudaGetSymbolAddress((void**)&tok2p,   s_tok2);
    cudaGetSymbolAddress((void**)&qkvwp,   s_qkvw);
    cudaGetSymbolAddress((void**)&projwp,  s_projw);
    cudaGetSymbolAddress((void**)&gatewp,  s_gatew);
    cudaGetSymbolAddress((void**)&upwp,    s_upw);
    cudaGetSymbolAddress((void**)&downwp,  s_downw);
    __nv_bfloat16* hidp;
    cudaGetSymbolAddress((void**)&hidp, s_hid);

    dim3 trGrid((Sn + 31) / 32, Cc / 32, Bn);
    dim3 trBlk(32, 8);

    // 0) weight conversions (run every call; graph-capturable)
    convert_split<<<512, 256>>>(qkv_w,  qkvwp,  P_QKVW,  P_QKVW / 4);
    convert_split<<<512, 256>>>(proj_w, projwp, P_PROJW, P_PROJW / 4);
    convert_split<<<512, 256>>>(gate_w, gatewp, P_GATEW, P_GATEW / 4);
    convert_split<<<512, 256>>>(up_w,   upwp,   P_GATEW, P_GATEW / 4);
    convert_split<<<512, 256>>>(down_w, downwp, P_DOWNW, P_DOWNW / 4);

    // 1) LayerNorm -> s_tok planes
    ln_reduce<<<dim3(64, Bn), 256>>>(x);
    ln_finalize<<<Bn, 64>>>();
    ln_apply_tr<<<trGrid, trBlk>>>(x, ln_w, ln_b);

    // 2) QKV -> s_qkv planes
    mma_gemm<false, true><<<dim3(18, 46, 1), 256, SMEM_BYTES>>>(
        tokp, P_TOK, qkvwp, P_QKVW, qkvp, P_QKV,
        BSn, C3, Cc, Cc, Cc, C3, C3,
        1, 0, 0, 0, 0, 0, 0);

    // 3) scores = Q @ K^T -> fp32 g_scores (ld = SLD)
    mma_gemm<true, false><<<dim3(6, 6, 64), 256, SMEM_BYTES>>>(
        qkvp, P_QKV, qkvp + Cc, P_QKV, scoresp, 0,
        Sn, Sn, DH, DH, C3, C3, SLD,
        NHn,
        (long long)Sn * C3, DH,
        (long long)Sn * C3, DH,
        (long long)NHn * Sn * SLD, (long long)Sn * SLD);

    // 4) softmax -> s_prob planes
    softmax_warp<<<64 * Sn / 8, 256>>>(scoresp);

    // 5) O = P @ V -> s_att planes (A K padded to 736, V rows valid to 729)
    mma_gemm<false, true><<<dim3(1, 6, 64), 256, SMEM_BYTES>>>(
        probp, P_PROB, qkvp + 2 * Cc, P_QKV, attp, P_TOK,
        Sn, DH, SLD, Sn, SLD, C3, Cc,
        NHn,
        (long long)NHn * Sn * SLD, (long long)Sn * SLD,
        (long long)Sn * C3, DH,
        (long long)Sn * Cc, DH);

    // 6) proj -> fp32 g_projo
    mma_gemm<false, false><<<dim3(6, 46, 1), 256, SMEM_BYTES>>>(
        attp, P_TOK, projwp, P_PROJW, projop, 0,
        BSn, Cc, Cc, Cc, Cc, Cc, Cc,
        1, 0, 0, 0, 0, 0, 0);

    // 7) x2 = x + po -> out, g_tok2, s_tok2 planes
    addproj_tr<<<trGrid, trBlk>>>(x, out);

    // 8) router
    router_kernel<<<Sn, 256>>>(router_w);

    // 9) gate/up per expert -> fp32
    mma_gemm<false, false><<<dim3(16, 46, En), 256, SMEM_BYTES>>>(
        tok2p, P_TOK, gatewp, P_GATEW, gp, 0,
        BSn, HIDn, Cc, Cc, Cc, HIDn, EH,
        1, 0, 0, (long long)Cc * HIDn, 0, HIDn, 0);
    mma_gemm<false, false><<<dim3(16, 46, En), 256, SMEM_BYTES>>>(
        tok2p, P_TOK, upwp, P_GATEW, up, 0,
        BSn, HIDn, Cc, Cc, Cc, HIDn, EH,
        1, 0, 0, (long long)Cc * HIDn, 0, HIDn, 0);

    // 10) silu -> s_hid planes
    silu_kernel<<<2048, 256>>>();

    // 11) down -> fp32 g_moeo
    mma_gemm<false, false><<<dim3(6, 46, 1), 256, SMEM_BYTES>>>(
        hidp, P_HID, downwp, P_DOWNW, moeop, 0,
        BSn, Cc, EH, EH, EH, Cc, Cc,
        1, 0, 0, 0, 0, 0, 0);

    // 12) out += mo
    addmoe_tr<<<trGrid, trBlk>>>(out);

    (void)in_sizes; (void)n_in; (void)out_size;
}

// round 9
// speedup vs baseline: 4.8422x; 1.2470x over previous
#include <cuda_runtime.h>
#include <cuda_bf16.h>
#include <math.h>
#include <stdint.h>

// ---------------------------------------------------------------------------
// Problem constants
// ---------------------------------------------------------------------------
#define Bn   8
#define Cc   768
#define Sn   729            // 9*9*9
#define SLD  736            // padded scores leading dim (= 23*32)
#define CS   (Cc * Sn)
#define NHn  8
#define DH   96
#define BSn  (Bn * Sn)      // 5832
#define HIDn 2048
#define En   3
#define C3   (3 * Cc)       // 2304
#define EH   (En * HIDn)    // 6144
#define EPSv 1e-5f

// plane element counts
#define P_TOK   ((long long)BSn * Cc)
#define P_QKV   ((long long)BSn * C3)
#define P_PROB  ((long long)64 * Sn * SLD)
#define P_HID   ((long long)En * BSn * HIDn)
#define P_QKVW  ((long long)Cc * C3)
#define P_PROJW ((long long)Cc * Cc)
#define P_GATEW ((long long)En * Cc * HIDn)
#define P_DOWNW ((long long)En * HIDn * Cc)

// ---------------------------------------------------------------------------
// Scratch (device globals)
// ---------------------------------------------------------------------------
__device__ float g_scores[64 * Sn * SLD];
__device__ float g_tok2 [BSn * Cc];
__device__ float g_projo[BSn * Cc];
__device__ float g_gbuf [En * BSn * HIDn];   // slot space [e][slot][HIDn]
__device__ float g_ubuf [En * BSn * HIDn];
__device__ float g_moeo [En * BSn * Cc];     // slot space per-expert down out
__device__ float g_wfull[BSn * En];
__device__ float g_part [Bn * 64 * 2];
__device__ float g_stats[Bn * 2];

// MoE routing compaction
__device__ int   g_eidx [En * BSn];   // [e][slot] -> token
__device__ int   g_slot [BSn * En];   // [t][e] -> slot or -1
__device__ float g_wslot[En * BSn];   // [e][slot] -> weight
__device__ int   g_cnt  [En];

// split bf16 planes: hi at [0], lo at [P]; +64 pad for benign overreads
__device__ __align__(16) __nv_bfloat16 s_tok  [2 * P_TOK + 64];
__device__ __align__(16) __nv_bfloat16 s_qkv  [2 * P_QKV + 64];
__device__ __align__(16) __nv_bfloat16 s_prob [2 * P_PROB + 64];
__device__ __align__(16) __nv_bfloat16 s_att  [2 * P_TOK + 64];
__device__ __align__(16) __nv_bfloat16 s_tok2 [2 * P_TOK + 64];
__device__ __align__(16) __nv_bfloat16 s_hid  [2 * P_HID + 64];
__device__ __align__(16) __nv_bfloat16 s_qkvw [2 * P_QKVW + 64];
__device__ __align__(16) __nv_bfloat16 s_projw[2 * P_PROJW + 64];
__device__ __align__(16) __nv_bfloat16 s_gatew[2 * P_GATEW + 64];
__device__ __align__(16) __nv_bfloat16 s_upw  [2 * P_GATEW + 64];
__device__ __align__(16) __nv_bfloat16 s_downw[2 * P_DOWNW + 64];

// ---------------------------------------------------------------------------
// split + mma helpers
// ---------------------------------------------------------------------------
__device__ __forceinline__ void split2(float x, float y, uint32_t& hi, uint32_t& lo) {
    uint32_t ux = __float_as_uint(x), uy = __float_as_uint(y);
    uint32_t hx = (ux + 0x7FFFu + ((ux >> 16) & 1u)) & 0xFFFF0000u;
    uint32_t hy = (uy + 0x7FFFu + ((uy >> 16) & 1u)) & 0xFFFF0000u;
    float rx = x - __uint_as_float(hx);
    float ry = y - __uint_as_float(hy);
    hi = (hx >> 16) | hy;
    asm("cvt.rn.bf16x2.f32 %0, %1, %2;" : "=r"(lo) : "f"(ry), "f"(rx));
}

__device__ __forceinline__ void split1(float x, __nv_bfloat16* h, __nv_bfloat16* l) {
    uint32_t ux = __float_as_uint(x);
    uint32_t hx = (ux + 0x7FFFu + ((ux >> 16) & 1u)) & 0xFFFF0000u;
    unsigned short hs = (unsigned short)(hx >> 16);
    *(unsigned short*)h = hs;
    *l = __float2bfloat16(x - __uint_as_float(hx));
}

__device__ __forceinline__ void mma_bf16(float* c, const uint32_t* a,
                                         uint32_t b0, uint32_t b1) {
    asm volatile(
        "mma.sync.aligned.m16n8k16.row.col.f32.bf16.bf16.f32 "
        "{%0,%1,%2,%3}, {%4,%5,%6,%7}, {%8,%9}, {%0,%1,%2,%3};\n"
        : "+f"(c[0]), "+f"(c[1]), "+f"(c[2]), "+f"(c[3])
        : "r"(a[0]), "r"(a[1]), "r"(a[2]), "r"(a[3]), "r"(b0), "r"(b1));
}

__device__ __forceinline__ void ldsm_x4(uint32_t* r, uint32_t addr) {
    asm volatile("ldmatrix.sync.aligned.m8n8.x4.shared.b16 {%0,%1,%2,%3}, [%4];"
                 : "=r"(r[0]), "=r"(r[1]), "=r"(r[2]), "=r"(r[3]) : "r"(addr));
}
__device__ __forceinline__ void ldsm_x4_t(uint32_t* r, uint32_t addr) {
    asm volatile("ldmatrix.sync.aligned.m8n8.x4.trans.shared.b16 {%0,%1,%2,%3}, [%4];"
                 : "=r"(r[0]), "=r"(r[1]), "=r"(r[2]), "=r"(r[3]) : "r"(addr));
}

__device__ __forceinline__ void cpa16(uint32_t dst, const void* src, bool p) {
    int sz = p ? 16 : 0;
    asm volatile("cp.async.cg.shared.global [%0], [%1], 16, %2;"
                 :: "r"(dst), "l"(src), "r"(sz));
}
#define CP_COMMIT() asm volatile("cp.async.commit_group;" ::: "memory")
#define CP_WAIT0()  asm volatile("cp.async.wait_group 0;" ::: "memory")

// SMEM layout (halves): per buffer [Ahi][Alo][Bhi][Blo], each RGN
#define ASTRh 40
#define BSTRk 136
#define RGN   5120
#define BUFH  (4 * RGN)
#define SMEM_BYTES (2 * BUFH * 2)   // 81920

// ---------------------------------------------------------------------------
// bf16x3 mma.sync GEMM on pre-split hi/lo planes; cp.async pipeline.
// Optional: ridx (A row indirection, per-z offset sR), Mdyn (dynamic M per z).
// ---------------------------------------------------------------------------
template <bool BT, bool OSPLIT>
__global__ void __launch_bounds__(256, 2)
mma_gemm(const __nv_bfloat16* __restrict__ A, long long asplit,
         const __nv_bfloat16* __restrict__ B, long long bsplit,
         void* __restrict__ Cv, long long csplit,
         const int* __restrict__ ridx, long long sR,
         const int* __restrict__ Mdyn,
         int M, int N, int K, int Kb, int lda, int ldb, int ldc,
         int zdiv,
         long long sA1, long long sA2,
         long long sB1, long long sB2,
         long long sC1, long long sC2) {
    extern __shared__ ushort smem[];
    uint32_t sbase = (uint32_t)__cvta_generic_to_shared(smem);

    int z = blockIdx.z;
    long long zq = z / zdiv, zr = z % zdiv;
    A += zq * sA1 + zr * sA2;
    B += zq * sB1 + zr * sB2;

    if (Mdyn) M = Mdyn[zq];
    int m0 = blockIdx.y * 128, n0 = blockIdx.x * 128;
    if (m0 >= M) return;

    int tid = threadIdx.x, wid = tid >> 5, lane = tid & 31;
    int gid = lane >> 2, tig = lane & 3;
    int wm = (wid & 3) * 32, wn = (wid >> 2) * 64;

    // A copy row prep (with optional indirection)
    const int* rp = ridx ? (ridx + zq * sR) : (const int*)0;
    int arow[2]; bool aval[2];
    #pragma unroll
    for (int p = 0; p < 2; p++) {
        int r = (tid >> 2) + p * 64;
        int gm = m0 + r;
        aval[p] = (gm < M);
        arow[p] = aval[p] ? (rp ? rp[gm] : gm) : 0;
    }

    // ldsm byte offsets within a buffer region
    uint32_t aoff[2];
    {
        int arow0 = wm + (lane & 15);
        int akc = (lane & 16) ? 8 : 0;
        aoff[0] = (uint32_t)((arow0)      * ASTRh + akc) * 2;
        aoff[1] = (uint32_t)((arow0 + 16) * ASTRh + akc) * 2;
    }
    uint32_t boff;
    if (BT) {
        int nrow0 = wn + (lane & 7) + ((lane & 16) ? 8 : 0);
        int bkc = (lane & 8) ? 8 : 0;
        boff = (uint32_t)(nrow0 * ASTRh + bkc) * 2;
    } else {
        int krow0 = (lane & 15);
        int ncol0 = wn + ((lane & 16) ? 8 : 0);
        boff = (uint32_t)(krow0 * BSTRk + ncol0) * 2;
    }

    float acc[2][8][4];
    #pragma unroll
    for (int i = 0; i < 2; i++)
        #pragma unroll
        for (int j = 0; j < 8; j++)
            #pragma unroll
            for (int q = 0; q < 4; q++) acc[i][j][q] = 0.f;

    auto cp_chunk = [&](int k0, int buf) {
        uint32_t bb = sbase + (uint32_t)buf * BUFH * 2;
        int seg = tid & 3;
        #pragma unroll
        for (int p = 0; p < 2; p++) {
            int r = (tid >> 2) + p * 64;
            const __nv_bfloat16* src = A + (size_t)arow[p] * lda + k0 + seg * 8;
            uint32_t d = bb + (uint32_t)(r * ASTRh + seg * 8) * 2;
            cpa16(d, src, aval[p]);
            cpa16(d + RGN * 2, src + asplit, aval[p]);
        }
        if (BT) {
            #pragma unroll
            for (int p = 0; p < 2; p++) {
                int r = (tid >> 2) + p * 64;
                int gn = n0 + r;
                const __nv_bfloat16* src = B + (size_t)gn * ldb + k0 + seg * 8;
                uint32_t d = bb + (uint32_t)(2 * RGN * 2)
                           + (uint32_t)(r * ASTRh + seg * 8) * 2;
                bool pr = (gn < N);
                cpa16(d, src, pr);
                cpa16(d + RGN * 2, src + bsplit, pr);
            }
        } else {
            #pragma unroll
            for (int p = 0; p < 2; p++) {
                int kr = (tid >> 4) + p * 16;
                int sg = tid & 15;
                int gk = k0 + kr;
                const __nv_bfloat16* src = B + (size_t)gk * ldb + n0 + sg * 8;
                uint32_t d = bb + (uint32_t)(2 * RGN * 2)
                           + (uint32_t)(kr * BSTRk + sg * 8) * 2;
                bool pr = (gk < Kb);
                cpa16(d, src, pr);
                cpa16(d + RGN * 2, src + bsplit, pr);
            }
        }
    };

    auto mmaphase = [&](int bufsel) {
        uint32_t base = sbase + (uint32_t)bufsel * BUFH * 2;
        uint32_t ah_b = base;
        uint32_t al_b = base + RGN * 2;
        uint32_t bh_b = base + 2 * RGN * 2;
        uint32_t bl_b = base + 3 * RGN * 2;
        #pragma unroll
        for (int ks = 0; ks < 2; ks++) {
            uint32_t ak = (uint32_t)(ks * 16 * 2);
            uint32_t ah[2][4], alr[2][4];
            #pragma unroll
            for (int i = 0; i < 2; i++) {
                ldsm_x4(ah[i], ah_b + aoff[i] + ak);
                ldsm_x4(alr[i], al_b + aoff[i] + ak);
            }
            #pragma unroll
            for (int jp = 0; jp < 4; jp++) {
                uint32_t bh[4], bl[4];
                if (BT) {
                    uint32_t off = boff + (uint32_t)(jp * 16 * ASTRh * 2) + ak;
                    ldsm_x4(bh, bh_b + off);
                    ldsm_x4(bl, bl_b + off);
                } else {
                    uint32_t off = boff + (uint32_t)(ks * 16 * BSTRk * 2)
                                 + (uint32_t)(jp * 32);
                    ldsm_x4_t(bh, bh_b + off);
                    ldsm_x4_t(bl, bl_b + off);
                }
                #pragma unroll
                for (int pass = 0; pass < 3; pass++) {
                    const uint32_t (*af)[4] = (pass == 2) ? alr : ah;
                    const uint32_t* bf = (pass == 1) ? bl : bh;
                    #pragma unroll
                    for (int i = 0; i < 2; i++)
                        #pragma unroll
                        for (int jj = 0; jj < 2; jj++)
                            mma_bf16(acc[i][jp * 2 + jj], af[i],
                                     bf[2 * jj], bf[2 * jj + 1]);
                }
            }
        }
    };

    int nchunk = K >> 5;   // callers guarantee K % 32 == 0
    cp_chunk(0, 0); CP_COMMIT();
    for (int ch = 0; ch < nchunk; ch++) {
        CP_WAIT0();
        __syncthreads();
        if (ch + 1 < nchunk) { cp_chunk((ch + 1) * 32, (ch + 1) & 1); CP_COMMIT(); }
        mmaphase(ch & 1);
    }

    // ---- epilogue ----
    if (OSPLIT) {
        __nv_bfloat16* Ch = (__nv_bfloat16*)Cv + zq * sC1 + zr * sC2;
        #pragma unroll
        for (int i = 0; i < 2; i++) {
            #pragma unroll
            for (int j = 0; j < 8; j++) {
                int gm0 = m0 + wm + i * 16 + gid;
                int gn = n0 + wn + j * 8 + tig * 2;
                if (gm0 < M && gn + 1 < N) {
                    uint32_t h, l;
                    split2(acc[i][j][0], acc[i][j][1], h, l);
                    *(uint32_t*)(Ch + (size_t)gm0 * ldc + gn) = h;
                    *(uint32_t*)(Ch + csplit + (size_t)gm0 * ldc + gn) = l;
                }
                int gm1 = gm0 + 8;
                if (gm1 < M && gn + 1 < N) {
                    uint32_t h, l;
                    split2(acc[i][j][2], acc[i][j][3], h, l);
                    *(uint32_t*)(Ch + (size_t)gm1 * ldc + gn) = h;
                    *(uint32_t*)(Ch + csplit + (size_t)gm1 * ldc + gn) = l;
                }
            }
        }
    } else {
        float* C = (float*)Cv + zq * sC1 + zr * sC2;
        #pragma unroll
        for (int i = 0; i < 2; i++) {
            #pragma unroll
            for (int j = 0; j < 8; j++) {
                int gm0 = m0 + wm + i * 16 + gid;
                int gn = n0 + wn + j * 8 + tig * 2;
                if (gm0 < M) {
                    if (gn + 1 < N) {
                        *(float2*)(C + (size_t)gm0 * ldc + gn) =
                            make_float2(acc[i][j][0], acc[i][j][1]);
                    } else if (gn < N) {
                        C[(size_t)gm0 * ldc + gn] = acc[i][j][0];
                    }
                }
                int gm1 = gm0 + 8;
                if (gm1 < M) {
                    if (gn + 1 < N) {
                        *(float2*)(C + (size_t)gm1 * ldc + gn) =
                            make_float2(acc[i][j][2], acc[i][j][3]);
                    } else if (gn < N) {
                        C[(size_t)gm1 * ldc + gn] = acc[i][j][2];
                    }
                }
            }
        }
    }
}

// ---------------------------------------------------------------------------
// fp32 -> split bf16 planes (weights)
// ---------------------------------------------------------------------------
__global__ void convert_split(const float* __restrict__ src,
                              __nv_bfloat16* __restrict__ dst,
                              long long psplit, long long n4) {
    for (long long i = (long long)blockIdx.x * blockDim.x + threadIdx.x; i < n4;
         i += (long long)gridDim.x * blockDim.x) {
        float4 v = ((const float4*)src)[i];
        uint32_t h01, l01, h23, l23;
        split2(v.x, v.y, h01, l01);
        split2(v.z, v.w, h23, l23);
        ((uint2*)dst)[i] = make_uint2(h01, h23);
        ((uint2*)(dst + psplit))[i] = make_uint2(l01, l23);
    }
}

// ---------------------------------------------------------------------------
// LayerNorm
// ---------------------------------------------------------------------------
__global__ void ln_reduce(const float* __restrict__ x) {
    int b = blockIdx.y;
    const float* xb = x + (size_t)b * CS;
    float s = 0.f, sq = 0.f;
    for (int i = blockIdx.x * blockDim.x + threadIdx.x; i < CS;
         i += gridDim.x * blockDim.x) {
        float v = xb[i];
        s += v; sq += v * v;
    }
    __shared__ float sh1[256], sh2[256];
    sh1[threadIdx.x] = s; sh2[threadIdx.x] = sq;
    __syncthreads();
    for (int o = 128; o > 0; o >>= 1) {
        if (threadIdx.x < o) {
            sh1[threadIdx.x] += sh1[threadIdx.x + o];
            sh2[threadIdx.x] += sh2[threadIdx.x + o];
        }
        __syncthreads();
    }
    if (threadIdx.x == 0) {
        g_part[(b * 64 + blockIdx.x) * 2 + 0] = sh1[0];
        g_part[(b * 64 + blockIdx.x) * 2 + 1] = sh2[0];
    }
}

__global__ void ln_finalize() {
    int b = blockIdx.x, t = threadIdx.x;   // 64 threads
    float s = g_part[(b * 64 + t) * 2 + 0];
    float sq = g_part[(b * 64 + t) * 2 + 1];
    for (int o = 16; o > 0; o >>= 1) {
        s  += __shfl_down_sync(0xffffffffu, s, o);
        sq += __shfl_down_sync(0xffffffffu, sq, o);
    }
    __shared__ float a0[2], a1[2];
    if ((t & 31) == 0) { a0[t >> 5] = s; a1[t >> 5] = sq; }
    __syncthreads();
    if (t == 0) {
        g_stats[b * 2 + 0] = a0[0] + a0[1];
        g_stats[b * 2 + 1] = a1[0] + a1[1];
    }
}

__global__ void ln_apply_tr(const float* __restrict__ x,
                            const float* __restrict__ lw,
                            const float* __restrict__ lb) {
    __shared__ float tile[32][33];
    int b = blockIdx.z;
    float mean = g_stats[b * 2 + 0] * (1.f / CS);
    float var  = g_stats[b * 2 + 1] * (1.f / CS) - mean * mean;
    float inv  = rsqrtf(var + EPSv);
    int s0 = blockIdx.x * 32, c0 = blockIdx.y * 32;
    #pragma unroll
    for (int i = 0; i < 4; i++) {
        int cl = threadIdx.y + i * 8;
        int s = s0 + threadIdx.x, c = c0 + cl;
        if (s < Sn && c < Cc) {
            size_t idx = (size_t)c * Sn + s;
            float v = (x[(size_t)b * CS + idx] - mean) * inv * lw[idx] + lb[idx];
            tile[cl][threadIdx.x] = v;
        }
    }
    __syncthreads();
    #pragma unroll
    for (int i = 0; i < 4; i++) {
        int sl = threadIdx.y + i * 8;
        int s = s0 + sl, c = c0 + threadIdx.x;
        if (s < Sn && c < Cc) {
            size_t ti = ((size_t)b * Sn + s) * Cc + c;
            split1(tile[threadIdx.x][sl], &s_tok[ti], &s_tok[P_TOK + ti]);
        }
    }
}

// ---------------------------------------------------------------------------
// Softmax: one warp per row; writes split prob planes.
// ---------------------------------------------------------------------------
__global__ void softmax_warp(const float* __restrict__ data) {
    int row_id = blockIdx.x * 8 + (threadIdx.x >> 5);
    int lane = threadIdx.x & 31;
    if (row_id >= 64 * Sn) return;
    const float* row = data + (size_t)row_id * SLD;
    float v[23];
    float m = -INFINITY;
    #pragma unroll
    for (int i = 0; i < 23; i++) {
        int idx = lane + i * 32;
        v[i] = (idx < Sn) ? row[idx] : -INFINITY;
        m = fmaxf(m, v[i]);
    }
    #pragma unroll
    for (int o = 16; o > 0; o >>= 1)
        m = fmaxf(m, __shfl_xor_sync(0xffffffffu, m, o));
    float sum = 0.f;
    #pragma unroll
    for (int i = 0; i < 23; i++) {
        float e = __expf(v[i] - m);
        v[i] = e; sum += e;
    }
    #pragma unroll
    for (int o = 16; o > 0; o >>= 1)
        sum += __shfl_xor_sync(0xffffffffu, sum, o);
    float inv = 1.f / sum;
    size_t base = (size_t)row_id * SLD + lane;
    #pragma unroll
    for (int i = 0; i < 23; i++) {
        size_t ti = base + i * 32;
        split1(v[i] * inv, &s_prob[ti], &s_prob[P_PROB + ti]);
    }
}

// ---------------------------------------------------------------------------
// x2 = x + proj_out -> out, g_tok2, s_tok2 planes
// ---------------------------------------------------------------------------
__global__ void addproj_tr(const float* __restrict__ x, float* __restrict__ out) {
    __shared__ float shx[32][33];
    __shared__ float shy[32][33];
    int b = blockIdx.z;
    int s0 = blockIdx.x * 32, c0 = blockIdx.y * 32;
    #pragma unroll
    for (int i = 0; i < 4; i++) {
        int cl = threadIdx.y + i * 8;
        int s = s0 + threadIdx.x, c = c0 + cl;
        if (s < Sn && c < Cc)
            shx[cl][threadIdx.x] = x[(size_t)b * CS + (size_t)c * Sn + s];
    }
    __syncthreads();
    #pragma unroll
    for (int i = 0; i < 4; i++) {
        int sl = threadIdx.y + i * 8;
        int s = s0 + sl, c = c0 + threadIdx.x;
        if (s < Sn && c < Cc) {
            size_t ti = ((size_t)b * Sn + s) * Cc + c;
            float v = shx[threadIdx.x][sl] + g_projo[ti];
            g_tok2[ti] = v;
            split1(v, &s_tok2[ti], &s_tok2[P_TOK + ti]);
            shy[threadIdx.x][sl] = v;
        }
    }
    __syncthreads();
    #pragma unroll
    for (int i = 0; i < 4; i++) {
        int cl = threadIdx.y + i * 8;
        int s = s0 + threadIdx.x, c = c0 + cl;
        if (s < Sn && c < Cc)
            out[(size_t)b * CS + (size_t)c * Sn + s] = shy[cl][threadIdx.x];
    }
}

// ---------------------------------------------------------------------------
// Router
// ---------------------------------------------------------------------------
__global__ void router_kernel(const float* __restrict__ rw) {
    int t = blockIdx.x * 8 + (threadIdx.x >> 5);
    int lane = threadIdx.x & 31;
    if (t >= BSn) return;
    const float* tk = g_tok2 + (size_t)t * Cc;
    float s0 = 0.f, s1 = 0.f, s2 = 0.f;
    for (int c = lane; c < Cc; c += 32) {
        float v = tk[c];
        s0 += v * rw[c * 3 + 0];
        s1 += v * rw[c * 3 + 1];
        s2 += v * rw[c * 3 + 2];
    }
    for (int o = 16; o > 0; o >>= 1) {
        s0 += __shfl_down_sync(0xffffffffu, s0, o);
        s1 += __shfl_down_sync(0xffffffffu, s1, o);
        s2 += __shfl_down_sync(0xffffffffu, s2, o);
    }
    if (lane == 0) {
        float m = fmaxf(s0, fmaxf(s1, s2));
        float p0 = __expf(s0 - m), p1 = __expf(s1 - m), p2 = __expf(s2 - m);
        float tot = p0 + p1 + p2;
        p0 /= tot; p1 /= tot; p2 /= tot;
        int amin = 0; float pm = p0;
        if (p1 <= pm) { amin = 1; pm = p1; }
        if (p2 <= pm) { amin = 2; pm = p2; }
        float denom = (p0 + p1 + p2) - pm;
        g_wfull[t * 3 + 0] = (amin == 0) ? 0.f : p0 / denom;
        g_wfull[t * 3 + 1] = (amin == 1) ? 0.f : p1 / denom;
        g_wfull[t * 3 + 2] = (amin == 2) ? 0.f : p2 / denom;
    }
}

// ---------------------------------------------------------------------------
// Deterministic per-expert compaction (1 block/expert, 1024 threads)
// ---------------------------------------------------------------------------
__global__ void compact_kernel() {
    int e = blockIdx.x;
    int tid = threadIdx.x;
    int lane = tid & 31, wr = tid >> 5;
    __shared__ int sh[32];
    __shared__ int sbase;
    if (tid == 0) sbase = 0;
    __syncthreads();
    for (int start = 0; start < BSn; start += 1024) {
        int t = start + tid;
        float w = (t < BSn) ? g_wfull[t * 3 + e] : 0.f;
        int flag = (w > 0.f) ? 1 : 0;
        int x = flag;
        #pragma unroll
        for (int o = 1; o < 32; o <<= 1) {
            int y = __shfl_up_sync(0xffffffffu, x, o);
            if (lane >= o) x += y;
        }
        if (lane == 31) sh[wr] = x;
        __syncthreads();
        if (wr == 0) {
            int v = sh[lane];
            #pragma unroll
            for (int o = 1; o < 32; o <<= 1) {
                int y = __shfl_up_sync(0xffffffffu, v, o);
                if (lane >= o) v += y;
            }
            sh[lane] = v;
        }
        __syncthreads();
        int warp_excl = wr ? sh[wr - 1] : 0;
        int pos = sbase + warp_excl + (x - flag);
        if (t < BSn) {
            if (flag) {
                g_eidx[e * BSn + pos] = t;
                g_slot[t * 3 + e] = pos;
                g_wslot[e * BSn + pos] = w;
            } else {
                g_slot[t * 3 + e] = -1;
            }
        }
        __syncthreads();
        if (tid == 0) sbase += sh[31];
        __syncthreads();
    }
    if (tid == 0) g_cnt[e] = sbase;
}

// ---------------------------------------------------------------------------
// hid = wslot * silu(g) * u -> split planes (slot space, skip dead slots)
// ---------------------------------------------------------------------------
__global__ void silu_kernel() {
    size_t n4 = (size_t)En * BSn * HIDn / 4;
    for (size_t i = (size_t)blockIdx.x * blockDim.x + threadIdx.x; i < n4;
         i += (size_t)gridDim.x * blockDim.x) {
        size_t base = i * 4;
        int row = (int)(base >> 11);          // [e*BSn + slot]
        int e = row / BSn, slot = row - e * BSn;
        if (slot >= g_cnt[e]) continue;
        float4 g = ((float4*)g_gbuf)[i];
        float4 u = ((float4*)g_ubuf)[i];
        float w = g_wslot[row];
        float4 r;
        r.x = w * (g.x / (1.f + __expf(-g.x))) * u.x;
        r.y = w * (g.y / (1.f + __expf(-g.y))) * u.y;
        r.z = w * (g.z / (1.f + __expf(-g.z))) * u.z;
        r.w = w * (g.w / (1.f + __expf(-g.w))) * u.w;
        uint32_t h01, l01, h23, l23;
        split2(r.x, r.y, h01, l01);
        split2(r.z, r.w, h23, l23);
        ((uint2*)s_hid)[i] = make_uint2(h01, h23);
        ((uint2*)(s_hid + P_HID))[i] = make_uint2(l01, l23);
    }
}

// ---------------------------------------------------------------------------
// out += sum_e moe_e (slot-space gather, fixed expert order) transposed
// ---------------------------------------------------------------------------
__global__ void addmoe_tr(float* __restrict__ out) {
    __shared__ float sh[32][33];
    int b = blockIdx.z;
    int s0 = blockIdx.x * 32, c0 = blockIdx.y * 32;
    #pragma unroll
    for (int i = 0; i < 4; i++) {
        int sl = threadIdx.y + i * 8;
        int s = s0 + sl, c = c0 + threadIdx.x;
        if (s < Sn && c < Cc) {
            int t = b * Sn + s;
            float acc = 0.f;
            #pragma unroll
            for (int e = 0; e < En; e++) {
                int slot = g_slot[t * 3 + e];
                if (slot >= 0)
                    acc += g_moeo[((size_t)e * BSn + slot) * Cc + c];
            }
            sh[threadIdx.x][sl] = acc;
        }
    }
    __syncthreads();
    #pragma unroll
    for (int i = 0; i < 4; i++) {
        int cl = threadIdx.y + i * 8;
        int s = s0 + threadIdx.x, c = c0 + cl;
        if (s < Sn && c < Cc) {
            size_t idx = (size_t)b * CS + (size_t)c * Sn + s;
            out[idx] += sh[cl][threadIdx.x];
        }
    }
}

// ---------------------------------------------------------------------------
// Host launcher
// ---------------------------------------------------------------------------
extern "C" void kernel_launch(void* const* d_in, const int* in_sizes, int n_in,
                              void* d_out, int out_size) {
    const float* x        = (const float*)d_in[0];
    const float* ln_w     = (const float*)d_in[1];
    const float* ln_b     = (const float*)d_in[2];
    const float* qkv_w    = (const float*)d_in[3];
    const float* proj_w   = (const float*)d_in[4];
    const float* router_w = (const float*)d_in[5];
    const float* gate_w   = (const float*)d_in[6];
    const float* up_w     = (const float*)d_in[7];
    const float* down_w   = (const float*)d_in[8];
    float* out = (float*)d_out;

    cudaFuncSetAttribute(mma_gemm<false, false>,
                         cudaFuncAttributeMaxDynamicSharedMemorySize, SMEM_BYTES);
    cudaFuncSetAttribute(mma_gemm<false, true>,
                         cudaFuncAttributeMaxDynamicSharedMemorySize, SMEM_BYTES);
    cudaFuncSetAttribute(mma_gemm<true, false>,
                         cudaFuncAttributeMaxDynamicSharedMemorySize, SMEM_BYTES);

    float *scoresp, *projop, *gp, *up, *moeop;
    __nv_bfloat16 *tokp, *qkvp, *probp, *attp, *tok2p, *hidp;
    __nv_bfloat16 *qkvwp, *projwp, *gatewp, *upwp, *downwp;
    int *eidxp, *cntp;
    cudaGetSymbolAddress((void**)&scoresp, g_scores);
    cudaGetSymbolAddress((void**)&projop,  g_projo);
    cudaGetSymbolAddress((void**)&gp,      g_gbuf);
    cudaGetSymbolAddress((void**)&up,      g_ubuf);
    cudaGetSymbolAddress((void**)&moeop,   g_moeo);
    cudaGetSymbolAddress((void**)&tokp,    s_tok);
    cudaGetSymbolAddress((void**)&qkvp,    s_qkv);
    cudaGetSymbolAddress((void**)&probp,   s_prob);
    cudaGetSymbolAddress((void**)&attp,    s_att);
    cudaGetSymbolAddress((void**)&tok2p,   s_tok2);
    cudaGetSymbolAddress((void**)&hidp,    s_hid);
    cudaGetSymbolAddress((void**)&qkvwp,   s_qkvw);
    cudaGetSymbolAddress((void**)&projwp,  s_projw);
    cudaGetSymbolAddress((void**)&gatewp,  s_gatew);
    cudaGetSymbolAddress((void**)&upwp,    s_upw);
    cudaGetSymbolAddress((void**)&downwp,  s_downw);
    cudaGetSymbolAddress((void**)&eidxp,   g_eidx);
    cudaGetSymbolAddress((void**)&cntp,    g_cnt);

    dim3 trGrid((Sn + 31) / 32, Cc / 32, Bn);
    dim3 trBlk(32, 8);

    // 0) weight conversions
    convert_split<<<512, 256>>>(qkv_w,  qkvwp,  P_QKVW,  P_QKVW / 4);
    convert_split<<<512, 256>>>(proj_w, projwp, P_PROJW, P_PROJW / 4);
    convert_split<<<512, 256>>>(gate_w, gatewp, P_GATEW, P_GATEW / 4);
    convert_split<<<512, 256>>>(up_w,   upwp,   P_GATEW, P_GATEW / 4);
    convert_split<<<512, 256>>>(down_w, downwp, P_DOWNW, P_DOWNW / 4);

    // 1) LayerNorm -> s_tok planes
    ln_reduce<<<dim3(64, Bn), 256>>>(x);
    ln_finalize<<<Bn, 64>>>();
    ln_apply_tr<<<trGrid, trBlk>>>(x, ln_w, ln_b);

    // 2) QKV -> s_qkv planes
    mma_gemm<false, true><<<dim3(18, 46, 1), 256, SMEM_BYTES>>>(
        tokp, P_TOK, qkvwp, P_QKVW, qkvp, P_QKV,
        nullptr, 0, nullptr,
        BSn, C3, Cc, Cc, Cc, C3, C3,
        1, 0, 0, 0, 0, 0, 0);

    // 3) scores = Q @ K^T -> fp32 g_scores (ld = SLD)
    mma_gemm<true, false><<<dim3(6, 6, 64), 256, SMEM_BYTES>>>(
        qkvp, P_QKV, qkvp + Cc, P_QKV, scoresp, 0,
        nullptr, 0, nullptr,
        Sn, Sn, DH, DH, C3, C3, SLD,
        NHn,
        (long long)Sn * C3, DH,
        (long long)Sn * C3, DH,
        (long long)NHn * Sn * SLD, (long long)Sn * SLD);

    // 4) softmax -> s_prob planes
    softmax_warp<<<64 * Sn / 8, 256>>>(scoresp);

    // 5) O = P @ V -> s_att planes
    mma_gemm<false, true><<<dim3(1, 6, 64), 256, SMEM_BYTES>>>(
        probp, P_PROB, qkvp + 2 * Cc, P_QKV, attp, P_TOK,
        nullptr, 0, nullptr,
        Sn, DH, SLD, Sn, SLD, C3, Cc,
        NHn,
        (long long)NHn * Sn * SLD, (long long)Sn * SLD,
        (long long)Sn * C3, DH,
        (long long)Sn * Cc, DH);

    // 6) proj -> fp32 g_projo
    mma_gemm<false, false><<<dim3(6, 46, 1), 256, SMEM_BYTES>>>(
        attp, P_TOK, projwp, P_PROJW, projop, 0,
        nullptr, 0, nullptr,
        BSn, Cc, Cc, Cc, Cc, Cc, Cc,
        1, 0, 0, 0, 0, 0, 0);

    // 7) x2 = x + po
    addproj_tr<<<trGrid, trBlk>>>(x, out);

    // 8) router + compaction
    router_kernel<<<Sn, 256>>>(router_w);
    compact_kernel<<<En, 1024>>>();

    // 9) gate/up per expert, A row-indirected, M = cnt[e]
    mma_gemm<false, false><<<dim3(16, 46, En), 256, SMEM_BYTES>>>(
        tok2p, P_TOK, gatewp, P_GATEW, gp, 0,
        eidxp, BSn, cntp,
        BSn, HIDn, Cc, Cc, Cc, HIDn, HIDn,
        1, 0, 0, (long long)Cc * HIDn, 0, (long long)BSn * HIDn, 0);
    mma_gemm<false, false><<<dim3(16, 46, En), 256, SMEM_BYTES>>>(
        tok2p, P_TOK, upwp, P_GATEW, up, 0,
        eidxp, BSn, cntp,
        BSn, HIDn, Cc, Cc, Cc, HIDn, HIDn,
        1, 0, 0, (long long)Cc * HIDn, 0, (long long)BSn * HIDn, 0);

    // 10) silu (slot space) -> s_hid planes
    silu_kernel<<<2048, 256>>>();

    // 11) down per expert: hid_e (cnt x 2048) @ down_w[e] -> g_moeo slot space
    mma_gemm<false, false><<<dim3(6, 46, En), 256, SMEM_BYTES>>>(
        hidp, P_HID, downwp, P_DOWNW, moeop, 0,
        nullptr, 0, cntp,
        BSn, Cc, HIDn, HIDn, HIDn, Cc, Cc,
        1, (long long)BSn * HIDn, 0,
        (long long)HIDn * Cc, 0,
        (long long)BSn * Cc, 0);

    // 12) out += sum_e moe_e (gathered)
    addmoe_tr<<<trGrid, trBlk>>>(out);

    (void)in_sizes; (void)n_in; (void)out_size;
}

// round 10
// speedup vs baseline: 4.9365x; 1.0195x over previous
#include <cuda_runtime.h>
#include <cuda_bf16.h>
#include <math.h>
#include <stdint.h>

// ---------------------------------------------------------------------------
// Problem constants
// ---------------------------------------------------------------------------
#define Bn   8
#define Cc   768
#define Sn   729            // 9*9*9
#define CS   (Cc * Sn)
#define NHn  8
#define DH   96
#define BSn  (Bn * Sn)      // 5832
#define HIDn 2048
#define En   3
#define C3   (3 * Cc)       // 2304
#define EPSv 1e-5f

// plane element counts
#define P_TOK   ((long long)BSn * Cc)
#define P_QKV   ((long long)BSn * C3)
#define P_HID   ((long long)En * BSn * HIDn)
#define P_QKVW  ((long long)Cc * C3)
#define P_PROJW ((long long)Cc * Cc)
#define P_GATEW ((long long)En * Cc * HIDn)
#define P_DOWNW ((long long)En * HIDn * Cc)

// ---------------------------------------------------------------------------
// Scratch (device globals)
// ---------------------------------------------------------------------------
__device__ float g_tok2 [BSn * Cc];
__device__ float g_projo[BSn * Cc];
__device__ float g_gbuf [En * BSn * HIDn];   // gate acts, slot space
__device__ float g_moeo [En * BSn * Cc];     // per-expert down out, slot space
__device__ float g_wfull[BSn * En];
__device__ float g_part [Bn * 64 * 2];
__device__ float g_stats[Bn * 2];

// MoE routing compaction
__device__ int   g_eidx [En * BSn];
__device__ int   g_slot [BSn * En];
__device__ float g_wslot[En * BSn];
__device__ int   g_cnt  [En];

// split bf16 planes: hi at [0], lo at [P]; +64 pad for benign overreads
__device__ __align__(16) __nv_bfloat16 s_tok  [2 * P_TOK + 64];
__device__ __align__(16) __nv_bfloat16 s_qkv  [2 * P_QKV + 64];
__device__ __align__(16) __nv_bfloat16 s_att  [2 * P_TOK + 64];
__device__ __align__(16) __nv_bfloat16 s_tok2 [2 * P_TOK + 64];
__device__ __align__(16) __nv_bfloat16 s_hid  [2 * P_HID + 64];
__device__ __align__(16) __nv_bfloat16 s_qkvw [2 * P_QKVW + 64];
__device__ __align__(16) __nv_bfloat16 s_projw[2 * P_PROJW + 64];
__device__ __align__(16) __nv_bfloat16 s_gatew[2 * P_GATEW + 64];
__device__ __align__(16) __nv_bfloat16 s_upw  [2 * P_GATEW + 64];
__device__ __align__(16) __nv_bfloat16 s_downw[2 * P_DOWNW + 64];

// ---------------------------------------------------------------------------
// split + mma helpers
// ---------------------------------------------------------------------------
__device__ __forceinline__ void split2(float x, float y, uint32_t& hi, uint32_t& lo) {
    uint32_t ux = __float_as_uint(x), uy = __float_as_uint(y);
    uint32_t hx = (ux + 0x7FFFu + ((ux >> 16) & 1u)) & 0xFFFF0000u;
    uint32_t hy = (uy + 0x7FFFu + ((uy >> 16) & 1u)) & 0xFFFF0000u;
    float rx = x - __uint_as_float(hx);
    float ry = y - __uint_as_float(hy);
    hi = (hx >> 16) | hy;
    asm("cvt.rn.bf16x2.f32 %0, %1, %2;" : "=r"(lo) : "f"(ry), "f"(rx));
}

__device__ __forceinline__ void split1(float x, __nv_bfloat16* h, __nv_bfloat16* l) {
    uint32_t ux = __float_as_uint(x);
    uint32_t hx = (ux + 0x7FFFu + ((ux >> 16) & 1u)) & 0xFFFF0000u;
    unsigned short hs = (unsigned short)(hx >> 16);
    *(unsigned short*)h = hs;
    *l = __float2bfloat16(x - __uint_as_float(hx));
}

__device__ __forceinline__ void mma_bf16(float* c, const uint32_t* a,
                                         uint32_t b0, uint32_t b1) {
    asm volatile(
        "mma.sync.aligned.m16n8k16.row.col.f32.bf16.bf16.f32 "
        "{%0,%1,%2,%3}, {%4,%5,%6,%7}, {%8,%9}, {%0,%1,%2,%3};\n"
        : "+f"(c[0]), "+f"(c[1]), "+f"(c[2]), "+f"(c[3])
        : "r"(a[0]), "r"(a[1]), "r"(a[2]), "r"(a[3]), "r"(b0), "r"(b1));
}

__device__ __forceinline__ void ldsm_x4(uint32_t* r, uint32_t addr) {
    asm volatile("ldmatrix.sync.aligned.m8n8.x4.shared.b16 {%0,%1,%2,%3}, [%4];"
                 : "=r"(r[0]), "=r"(r[1]), "=r"(r[2]), "=r"(r[3]) : "r"(addr));
}
__device__ __forceinline__ void ldsm_x4_t(uint32_t* r, uint32_t addr) {
    asm volatile("ldmatrix.sync.aligned.m8n8.x4.trans.shared.b16 {%0,%1,%2,%3}, [%4];"
                 : "=r"(r[0]), "=r"(r[1]), "=r"(r[2]), "=r"(r[3]) : "r"(addr));
}

__device__ __forceinline__ void cpa16(uint32_t dst, const void* src, bool p) {
    int sz = p ? 16 : 0;
    asm volatile("cp.async.cg.shared.global [%0], [%1], 16, %2;"
                 :: "r"(dst), "l"(src), "r"(sz));
}
#define CP_COMMIT() asm volatile("cp.async.commit_group;" ::: "memory")
#define CP_WAIT0()  asm volatile("cp.async.wait_group 0;" ::: "memory")

// GEMM SMEM layout (halves): per buffer [Ahi][Alo][Bhi][Blo], each RGN
#define ASTRh 40
#define BSTRk 136
#define RGN   5120
#define BUFH  (4 * RGN)
#define SMEM_BYTES (2 * BUFH * 2)   // 81920

// ---------------------------------------------------------------------------
// bf16x3 mma.sync GEMM on pre-split hi/lo planes; cp.async pipeline.
// MODE: 0 = fp32 out, 1 = split bf16 out, 2 = silu-fused split out
//   (MODE 2: out = w * silu(g) * acc, g from Gv (same layout as C), w from Wv)
// ---------------------------------------------------------------------------
template <bool BT, int MODE>
__global__ void __launch_bounds__(256, 2)
mma_gemm(const __nv_bfloat16* __restrict__ A, long long asplit,
         const __nv_bfloat16* __restrict__ B, long long bsplit,
         void* __restrict__ Cv, long long csplit,
         const float* __restrict__ Gv, const float* __restrict__ Wv,
         const int* __restrict__ ridx, long long sR,
         const int* __restrict__ Mdyn,
         int M, int N, int K, int Kb, int lda, int ldb, int ldc,
         int zdiv,
         long long sA1, long long sA2,
         long long sB1, long long sB2,
         long long sC1, long long sC2) {
    extern __shared__ ushort smem[];
    uint32_t sbase = (uint32_t)__cvta_generic_to_shared(smem);

    int z = blockIdx.z;
    long long zq = z / zdiv, zr = z % zdiv;
    A += zq * sA1 + zr * sA2;
    B += zq * sB1 + zr * sB2;

    if (Mdyn) M = Mdyn[zq];
    int m0 = blockIdx.y * 128, n0 = blockIdx.x * 128;
    if (m0 >= M) return;

    int tid = threadIdx.x, wid = tid >> 5, lane = tid & 31;
    int gid = lane >> 2, tig = lane & 3;
    int wm = (wid & 3) * 32, wn = (wid >> 2) * 64;

    const int* rp = ridx ? (ridx + zq * sR) : (const int*)0;
    int arow[2]; bool aval[2];
    #pragma unroll
    for (int p = 0; p < 2; p++) {
        int r = (tid >> 2) + p * 64;
        int gm = m0 + r;
        aval[p] = (gm < M);
        arow[p] = aval[p] ? (rp ? rp[gm] : gm) : 0;
    }

    uint32_t aoff[2];
    {
        int arow0 = wm + (lane & 15);
        int akc = (lane & 16) ? 8 : 0;
        aoff[0] = (uint32_t)((arow0)      * ASTRh + akc) * 2;
        aoff[1] = (uint32_t)((arow0 + 16) * ASTRh + akc) * 2;
    }
    uint32_t boff;
    if (BT) {
        int nrow0 = wn + (lane & 7) + ((lane & 16) ? 8 : 0);
        int bkc = (lane & 8) ? 8 : 0;
        boff = (uint32_t)(nrow0 * ASTRh + bkc) * 2;
    } else {
        int krow0 = (lane & 15);
        int ncol0 = wn + ((lane & 16) ? 8 : 0);
        boff = (uint32_t)(krow0 * BSTRk + ncol0) * 2;
    }

    float acc[2][8][4];
    #pragma unroll
    for (int i = 0; i < 2; i++)
        #pragma unroll
        for (int j = 0; j < 8; j++)
            #pragma unroll
            for (int q = 0; q < 4; q++) acc[i][j][q] = 0.f;

    auto cp_chunk = [&](int k0, int buf) {
        uint32_t bb = sbase + (uint32_t)buf * BUFH * 2;
        int seg = tid & 3;
        #pragma unroll
        for (int p = 0; p < 2; p++) {
            int r = (tid >> 2) + p * 64;
            const __nv_bfloat16* src = A + (size_t)arow[p] * lda + k0 + seg * 8;
            uint32_t d = bb + (uint32_t)(r * ASTRh + seg * 8) * 2;
            cpa16(d, src, aval[p]);
            cpa16(d + RGN * 2, src + asplit, aval[p]);
        }
        if (BT) {
            #pragma unroll
            for (int p = 0; p < 2; p++) {
                int r = (tid >> 2) + p * 64;
                int gn = n0 + r;
                const __nv_bfloat16* src = B + (size_t)gn * ldb + k0 + seg * 8;
                uint32_t d = bb + (uint32_t)(2 * RGN * 2)
                           + (uint32_t)(r * ASTRh + seg * 8) * 2;
                bool pr = (gn < N);
                cpa16(d, src, pr);
                cpa16(d + RGN * 2, src + bsplit, pr);
            }
        } else {
            #pragma unroll
            for (int p = 0; p < 2; p++) {
                int kr = (tid >> 4) + p * 16;
                int sg = tid & 15;
                int gk = k0 + kr;
                const __nv_bfloat16* src = B + (size_t)gk * ldb + n0 + sg * 8;
                uint32_t d = bb + (uint32_t)(2 * RGN * 2)
                           + (uint32_t)(kr * BSTRk + sg * 8) * 2;
                bool pr = (gk < Kb);
                cpa16(d, src, pr);
                cpa16(d + RGN * 2, src + bsplit, pr);
            }
        }
    };

    auto mmaphase = [&](int bufsel) {
        uint32_t base = sbase + (uint32_t)bufsel * BUFH * 2;
        uint32_t ah_b = base;
        uint32_t al_b = base + RGN * 2;
        uint32_t bh_b = base + 2 * RGN * 2;
        uint32_t bl_b = base + 3 * RGN * 2;
        #pragma unroll
        for (int ks = 0; ks < 2; ks++) {
            uint32_t ak = (uint32_t)(ks * 16 * 2);
            uint32_t ah[2][4], alr[2][4];
            #pragma unroll
            for (int i = 0; i < 2; i++) {
                ldsm_x4(ah[i], ah_b + aoff[i] + ak);
                ldsm_x4(alr[i], al_b + aoff[i] + ak);
            }
            #pragma unroll
            for (int jp = 0; jp < 4; jp++) {
                uint32_t bh[4], bl[4];
                if (BT) {
                    uint32_t off = boff + (uint32_t)(jp * 16 * ASTRh * 2) + ak;
                    ldsm_x4(bh, bh_b + off);
                    ldsm_x4(bl, bl_b + off);
                } else {
                    uint32_t off = boff + (uint32_t)(ks * 16 * BSTRk * 2)
                                 + (uint32_t)(jp * 32);
                    ldsm_x4_t(bh, bh_b + off);
                    ldsm_x4_t(bl, bl_b + off);
                }
                #pragma unroll
                for (int pass = 0; pass < 3; pass++) {
                    const uint32_t (*af)[4] = (pass == 2) ? alr : ah;
                    const uint32_t* bf = (pass == 1) ? bl : bh;
                    #pragma unroll
                    for (int i = 0; i < 2; i++)
                        #pragma unroll
                        for (int jj = 0; jj < 2; jj++)
                            mma_bf16(acc[i][jp * 2 + jj], af[i],
                                     bf[2 * jj], bf[2 * jj + 1]);
                }
            }
        }
    };

    int nchunk = K >> 5;
    cp_chunk(0, 0); CP_COMMIT();
    for (int ch = 0; ch < nchunk; ch++) {
        CP_WAIT0();
        __syncthreads();
        if (ch + 1 < nchunk) { cp_chunk((ch + 1) * 32, (ch + 1) & 1); CP_COMMIT(); }
        mmaphase(ch & 1);
    }

    // ---- epilogue ----
    if (MODE == 1) {
        __nv_bfloat16* Ch = (__nv_bfloat16*)Cv + zq * sC1 + zr * sC2;
        #pragma unroll
        for (int i = 0; i < 2; i++) {
            #pragma unroll
            for (int j = 0; j < 8; j++) {
                int gm0 = m0 + wm + i * 16 + gid;
                int gn = n0 + wn + j * 8 + tig * 2;
                if (gm0 < M && gn + 1 < N) {
                    uint32_t h, l;
                    split2(acc[i][j][0], acc[i][j][1], h, l);
                    *(uint32_t*)(Ch + (size_t)gm0 * ldc + gn) = h;
                    *(uint32_t*)(Ch + csplit + (size_t)gm0 * ldc + gn) = l;
                }
                int gm1 = gm0 + 8;
                if (gm1 < M && gn + 1 < N) {
                    uint32_t h, l;
                    split2(acc[i][j][2], acc[i][j][3], h, l);
                    *(uint32_t*)(Ch + (size_t)gm1 * ldc + gn) = h;
                    *(uint32_t*)(Ch + csplit + (size_t)gm1 * ldc + gn) = l;
                }
            }
        }
    } else if (MODE == 2) {
        __nv_bfloat16* Ch = (__nv_bfloat16*)Cv + zq * sC1 + zr * sC2;
        const float* Gp = Gv + zq * sC1 + zr * sC2;
        const float* Wp = Wv + zq * (long long)BSn;
        #pragma unroll
        for (int i = 0; i < 2; i++) {
            #pragma unroll
            for (int j = 0; j < 8; j++) {
                int gm0 = m0 + wm + i * 16 + gid;
                int gn = n0 + wn + j * 8 + tig * 2;
                if (gm0 < M && gn + 1 < N) {
                    float2 g2 = *(const float2*)(Gp + (size_t)gm0 * ldc + gn);
                    float w = Wp[gm0];
                    float r0 = w * (g2.x / (1.f + __expf(-g2.x))) * acc[i][j][0];
                    float r1 = w * (g2.y / (1.f + __expf(-g2.y))) * acc[i][j][1];
                    uint32_t h, l;
                    split2(r0, r1, h, l);
                    *(uint32_t*)(Ch + (size_t)gm0 * ldc + gn) = h;
                    *(uint32_t*)(Ch + csplit + (size_t)gm0 * ldc + gn) = l;
                }
                int gm1 = gm0 + 8;
                if (gm1 < M && gn + 1 < N) {
                    float2 g2 = *(const float2*)(Gp + (size_t)gm1 * ldc + gn);
                    float w = Wp[gm1];
                    float r0 = w * (g2.x / (1.f + __expf(-g2.x))) * acc[i][j][2];
                    float r1 = w * (g2.y / (1.f + __expf(-g2.y))) * acc[i][j][3];
                    uint32_t h, l;
                    split2(r0, r1, h, l);
                    *(uint32_t*)(Ch + (size_t)gm1 * ldc + gn) = h;
                    *(uint32_t*)(Ch + csplit + (size_t)gm1 * ldc + gn) = l;
                }
            }
        }
    } else {
        float* C = (float*)Cv + zq * sC1 + zr * sC2;
        #pragma unroll
        for (int i = 0; i < 2; i++) {
            #pragma unroll
            for (int j = 0; j < 8; j++) {
                int gm0 = m0 + wm + i * 16 + gid;
                int gn = n0 + wn + j * 8 + tig * 2;
                if (gm0 < M && gn + 1 < N)
                    *(float2*)(C + (size_t)gm0 * ldc + gn) =
                        make_float2(acc[i][j][0], acc[i][j][1]);
                int gm1 = gm0 + 8;
                if (gm1 < M && gn + 1 < N)
                    *(float2*)(C + (size_t)gm1 * ldc + gn) =
                        make_float2(acc[i][j][2], acc[i][j][3]);
            }
        }
    }
}

// ---------------------------------------------------------------------------
// Flash attention: per (b,h), Q-tile 128 x 96; stream K/V tiles of 128.
// bf16x3 for both QK^T and PV; online softmax in registers.
// ---------------------------------------------------------------------------
#define QSTR 104
#define FPLN (128 * QSTR)
#define FSMEM_BYTES (6 * FPLN * 2)   // 159744

__global__ void __launch_bounds__(256, 1)
flash_attn() {
    extern __shared__ ushort fs[];
    uint32_t sb = (uint32_t)__cvta_generic_to_shared(fs);
    int tid = threadIdx.x, wid = tid >> 5, lane = tid & 31;
    int gid = lane >> 2, tig = lane & 3;
    int bh = blockIdx.y, b = bh >> 3, h = bh & 7;
    int m0 = blockIdx.x * 128;
    int wm = wid * 16;

    const __nv_bfloat16* Qb = s_qkv + (size_t)b * Sn * C3 + h * DH;
    const __nv_bfloat16* Kb = Qb + Cc;
    const __nv_bfloat16* Vb = Qb + 2 * Cc;

    uint32_t pQh = sb,               pQl = sb + 1 * FPLN * 2;
    uint32_t pKh = sb + 2 * FPLN * 2, pKl = sb + 3 * FPLN * 2;
    uint32_t pVh = sb + 4 * FPLN * 2, pVl = sb + 5 * FPLN * 2;

    // load Q tile once
    {
        int r = tid >> 1, half = tid & 1;
        bool pr = (m0 + r) < Sn;
        const __nv_bfloat16* src = Qb + (size_t)(m0 + (pr ? r : 0)) * C3;
        uint32_t drow = (uint32_t)(r * QSTR) * 2;
        #pragma unroll
        for (int s = 0; s < 6; s++) {
            int seg = half * 6 + s;
            cpa16(pQh + drow + seg * 16, src + seg * 8, pr);
            cpa16(pQl + drow + seg * 16, src + P_QKV + seg * 8, pr);
        }
    }
    CP_COMMIT();

    uint32_t aoff = (uint32_t)((wm + (lane & 15)) * QSTR + ((lane & 16) ? 8 : 0)) * 2;
    uint32_t koff = (uint32_t)(((lane & 7) + ((lane & 16) ? 8 : 0)) * QSTR
                               + ((lane & 8) ? 8 : 0)) * 2;
    uint32_t voff = (uint32_t)((lane & 15) * QSTR + ((lane & 16) ? 8 : 0)) * 2;

    float m0r = -1e30f, m1r = -1e30f, l0 = 0.f, l1 = 0.f;
    float O[12][4];
    #pragma unroll
    for (int jo = 0; jo < 12; jo++)
        #pragma unroll
        for (int q = 0; q < 4; q++) O[jo][q] = 0.f;

    for (int it = 0; it < 6; it++) {
        int kv0 = it * 128;
        if (it) __syncthreads();   // all reads of previous K/V done
        {
            int r = tid >> 1, half = tid & 1;
            bool pr = (kv0 + r) < Sn;
            int rr = pr ? r : 0;
            const __nv_bfloat16* ks = Kb + (size_t)(kv0 + rr) * C3;
            const __nv_bfloat16* vs = Vb + (size_t)(kv0 + rr) * C3;
            uint32_t drow = (uint32_t)(r * QSTR) * 2;
            #pragma unroll
            for (int s = 0; s < 6; s++) {
                int seg = half * 6 + s;
                cpa16(pKh + drow + seg * 16, ks + seg * 8, pr);
                cpa16(pKl + drow + seg * 16, ks + P_QKV + seg * 8, pr);
                cpa16(pVh + drow + seg * 16, vs + seg * 8, pr);
                cpa16(pVl + drow + seg * 16, vs + P_QKV + seg * 8, pr);
            }
        }
        CP_COMMIT(); CP_WAIT0(); __syncthreads();

        // S = Q K^T (16 x 128 per warp)
        float S[16][4];
        #pragma unroll
        for (int nf = 0; nf < 16; nf++)
            #pragma unroll
            for (int q = 0; q < 4; q++) S[nf][q] = 0.f;
        #pragma unroll
        for (int ks = 0; ks < 6; ks++) {
            uint32_t ak = (uint32_t)(ks * 16 * 2);
            uint32_t ah[4], al[4];
            ldsm_x4(ah, pQh + aoff + ak);
            ldsm_x4(al, pQl + aoff + ak);
            #pragma unroll
            for (int p = 0; p < 8; p++) {
                uint32_t off = koff + (uint32_t)(p * 16 * QSTR * 2) + ak;
                uint32_t kh4[4], kl4[4];
                ldsm_x4(kh4, pKh + off);
                ldsm_x4(kl4, pKl + off);
                #pragma unroll
                for (int jj = 0; jj < 2; jj++) {
                    float* c = S[p * 2 + jj];
                    mma_bf16(c, ah, kh4[2 * jj], kh4[2 * jj + 1]);
                    mma_bf16(c, ah, kl4[2 * jj], kl4[2 * jj + 1]);
                    mma_bf16(c, al, kh4[2 * jj], kh4[2 * jj + 1]);
                }
            }
        }

        // mask + row max
        float mx0 = -1e30f, mx1 = -1e30f;
        #pragma unroll
        for (int nf = 0; nf < 16; nf++) {
            int c0 = kv0 + nf * 8 + tig * 2;
            if (c0 >= Sn)     { S[nf][0] = -1e30f; S[nf][2] = -1e30f; }
            if (c0 + 1 >= Sn) { S[nf][1] = -1e30f; S[nf][3] = -1e30f; }
            mx0 = fmaxf(mx0, fmaxf(S[nf][0], S[nf][1]));
            mx1 = fmaxf(mx1, fmaxf(S[nf][2], S[nf][3]));
        }
        mx0 = fmaxf(mx0, __shfl_xor_sync(0xffffffffu, mx0, 1));
        mx0 = fmaxf(mx0, __shfl_xor_sync(0xffffffffu, mx0, 2));
        mx1 = fmaxf(mx1, __shfl_xor_sync(0xffffffffu, mx1, 1));
        mx1 = fmaxf(mx1, __shfl_xor_sync(0xffffffffu, mx1, 2));

        float mn0 = fmaxf(m0r, mx0), mn1 = fmaxf(m1r, mx1);
        float al0 = __expf(m0r - mn0), al1 = __expf(m1r - mn1);
        m0r = mn0; m1r = mn1;

        float rs0 = 0.f, rs1 = 0.f;
        #pragma unroll
        for (int nf = 0; nf < 16; nf++) {
            S[nf][0] = __expf(S[nf][0] - mn0); rs0 += S[nf][0];
            S[nf][1] = __expf(S[nf][1] - mn0); rs0 += S[nf][1];
            S[nf][2] = __expf(S[nf][2] - mn1); rs1 += S[nf][2];
            S[nf][3] = __expf(S[nf][3] - mn1); rs1 += S[nf][3];
        }
        rs0 += __shfl_xor_sync(0xffffffffu, rs0, 1);
        rs0 += __shfl_xor_sync(0xffffffffu, rs0, 2);
        rs1 += __shfl_xor_sync(0xffffffffu, rs1, 1);
        rs1 += __shfl_xor_sync(0xffffffffu, rs1, 2);
        l0 = l0 * al0 + rs0;
        l1 = l1 * al1 + rs1;
        #pragma unroll
        for (int jo = 0; jo < 12; jo++) {
            O[jo][0] *= al0; O[jo][1] *= al0;
            O[jo][2] *= al1; O[jo][3] *= al1;
        }

        // O += P V (P from S in registers, bf16 split)
        #pragma unroll
        for (int kf = 0; kf < 8; kf++) {
            uint32_t ph[4], pl[4];
            split2(S[2 * kf][0],     S[2 * kf][1],     ph[0], pl[0]);
            split2(S[2 * kf][2],     S[2 * kf][3],     ph[1], pl[1]);
            split2(S[2 * kf + 1][0], S[2 * kf + 1][1], ph[2], pl[2]);
            split2(S[2 * kf + 1][2], S[2 * kf + 1][3], ph[3], pl[3]);
            #pragma unroll
            for (int p = 0; p < 6; p++) {
                uint32_t off = voff + (uint32_t)(kf * 16 * QSTR * 2)
                             + (uint32_t)(p * 32);
                uint32_t vh4[4], vl4[4];
                ldsm_x4_t(vh4, pVh + off);
                ldsm_x4_t(vl4, pVl + off);
                #pragma unroll
                for (int jj = 0; jj < 2; jj++) {
                    float* c = O[p * 2 + jj];
                    mma_bf16(c, ph, vh4[2 * jj], vh4[2 * jj + 1]);
                    mma_bf16(c, ph, vl4[2 * jj], vl4[2 * jj + 1]);
                    mma_bf16(c, pl, vh4[2 * jj], vh4[2 * jj + 1]);
                }
            }
        }
    }

    // finalize: O /= l; write split planes to s_att
    float inv0 = 1.f / l0, inv1 = 1.f / l1;
    int r0 = m0 + wm + gid, r1 = r0 + 8;
    #pragma unroll
    for (int jo = 0; jo < 12; jo++) {
        int col = h * DH + jo * 8 + tig * 2;
        if (r0 < Sn) {
            size_t ti = ((size_t)b * Sn + r0) * Cc + col;
            uint32_t hh, ll;
            split2(O[jo][0] * inv0, O[jo][1] * inv0, hh, ll);
            *(uint32_t*)(s_att + ti) = hh;
            *(uint32_t*)(s_att + P_TOK + ti) = ll;
        }
        if (r1 < Sn) {
            size_t ti = ((size_t)b * Sn + r1) * Cc + col;
            uint32_t hh, ll;
            split2(O[jo][2] * inv1, O[jo][3] * inv1, hh, ll);
            *(uint32_t*)(s_att + ti) = hh;
            *(uint32_t*)(s_att + P_TOK + ti) = ll;
        }
    }
}

// ---------------------------------------------------------------------------
// fp32 -> split bf16 planes (weights)
// ---------------------------------------------------------------------------
__global__ void convert_split(const float* __restrict__ src,
                              __nv_bfloat16* __restrict__ dst,
                              long long psplit, long long n4) {
    for (long long i = (long long)blockIdx.x * blockDim.x + threadIdx.x; i < n4;
         i += (long long)gridDim.x * blockDim.x) {
        float4 v = ((const float4*)src)[i];
        uint32_t h01, l01, h23, l23;
        split2(v.x, v.y, h01, l01);
        split2(v.z, v.w, h23, l23);
        ((uint2*)dst)[i] = make_uint2(h01, h23);
        ((uint2*)(dst + psplit))[i] = make_uint2(l01, l23);
    }
}

// ---------------------------------------------------------------------------
// LayerNorm
// ---------------------------------------------------------------------------
__global__ void ln_reduce(const float* __restrict__ x) {
    int b = blockIdx.y;
    const float* xb = x + (size_t)b * CS;
    float s = 0.f, sq = 0.f;
    for (int i = blockIdx.x * blockDim.x + threadIdx.x; i < CS;
         i += gridDim.x * blockDim.x) {
        float v = xb[i];
        s += v; sq += v * v;
    }
    __shared__ float sh1[256], sh2[256];
    sh1[threadIdx.x] = s; sh2[threadIdx.x] = sq;
    __syncthreads();
    for (int o = 128; o > 0; o >>= 1) {
        if (threadIdx.x < o) {
            sh1[threadIdx.x] += sh1[threadIdx.x + o];
            sh2[threadIdx.x] += sh2[threadIdx.x + o];
        }
        __syncthreads();
    }
    if (threadIdx.x == 0) {
        g_part[(b * 64 + blockIdx.x) * 2 + 0] = sh1[0];
        g_part[(b * 64 + blockIdx.x) * 2 + 1] = sh2[0];
    }
}

__global__ void ln_finalize() {
    int b = blockIdx.x, t = threadIdx.x;   // 64 threads
    float s = g_part[(b * 64 + t) * 2 + 0];
    float sq = g_part[(b * 64 + t) * 2 + 1];
    for (int o = 16; o > 0; o >>= 1) {
        s  += __shfl_down_sync(0xffffffffu, s, o);
        sq += __shfl_down_sync(0xffffffffu, sq, o);
    }
    __shared__ float a0[2], a1[2];
    if ((t & 31) == 0) { a0[t >> 5] = s; a1[t >> 5] = sq; }
    __syncthreads();
    if (t == 0) {
        g_stats[b * 2 + 0] = a0[0] + a0[1];
        g_stats[b * 2 + 1] = a1[0] + a1[1];
    }
}

__global__ void ln_apply_tr(const float* __restrict__ x,
                            const float* __restrict__ lw,
                            const float* __restrict__ lb) {
    __shared__ float tile[32][33];
    int b = blockIdx.z;
    float mean = g_stats[b * 2 + 0] * (1.f / CS);
    float var  = g_stats[b * 2 + 1] * (1.f / CS) - mean * mean;
    float inv  = rsqrtf(var + EPSv);
    int s0 = blockIdx.x * 32, c0 = blockIdx.y * 32;
    #pragma unroll
    for (int i = 0; i < 4; i++) {
        int cl = threadIdx.y + i * 8;
        int s = s0 + threadIdx.x, c = c0 + cl;
        if (s < Sn && c < Cc) {
            size_t idx = (size_t)c * Sn + s;
            float v = (x[(size_t)b * CS + idx] - mean) * inv * lw[idx] + lb[idx];
            tile[cl][threadIdx.x] = v;
        }
    }
    __syncthreads();
    #pragma unroll
    for (int i = 0; i < 4; i++) {
        int sl = threadIdx.y + i * 8;
        int s = s0 + sl, c = c0 + threadIdx.x;
        if (s < Sn && c < Cc) {
            size_t ti = ((size_t)b * Sn + s) * Cc + c;
            split1(tile[threadIdx.x][sl], &s_tok[ti], &s_tok[P_TOK + ti]);
        }
    }
}

// ---------------------------------------------------------------------------
// x2 = x + proj_out -> out, g_tok2, s_tok2 planes
// ---------------------------------------------------------------------------
__global__ void addproj_tr(const float* __restrict__ x, float* __restrict__ out) {
    __shared__ float shx[32][33];
    __shared__ float shy[32][33];
    int b = blockIdx.z;
    int s0 = blockIdx.x * 32, c0 = blockIdx.y * 32;
    #pragma unroll
    for (int i = 0; i < 4; i++) {
        int cl = threadIdx.y + i * 8;
        int s = s0 + threadIdx.x, c = c0 + cl;
        if (s < Sn && c < Cc)
            shx[cl][threadIdx.x] = x[(size_t)b * CS + (size_t)c * Sn + s];
    }
    __syncthreads();
    #pragma unroll
    for (int i = 0; i < 4; i++) {
        int sl = threadIdx.y + i * 8;
        int s = s0 + sl, c = c0 + threadIdx.x;
        if (s < Sn && c < Cc) {
            size_t ti = ((size_t)b * Sn + s) * Cc + c;
            float v = shx[threadIdx.x][sl] + g_projo[ti];
            g_tok2[ti] = v;
            split1(v, &s_tok2[ti], &s_tok2[P_TOK + ti]);
            shy[threadIdx.x][sl] = v;
        }
    }
    __syncthreads();
    #pragma unroll
    for (int i = 0; i < 4; i++) {
        int cl = threadIdx.y + i * 8;
        int s = s0 + threadIdx.x, c = c0 + cl;
        if (s < Sn && c < Cc)
            out[(size_t)b * CS + (size_t)c * Sn + s] = shy[cl][threadIdx.x];
    }
}

// ---------------------------------------------------------------------------
// Router
// ---------------------------------------------------------------------------
__global__ void router_kernel(const float* __restrict__ rw) {
    int t = blockIdx.x * 8 + (threadIdx.x >> 5);
    int lane = threadIdx.x & 31;
    if (t >= BSn) return;
    const float* tk = g_tok2 + (size_t)t * Cc;
    float s0 = 0.f, s1 = 0.f, s2 = 0.f;
    for (int c = lane; c < Cc; c += 32) {
        float v = tk[c];
        s0 += v * rw[c * 3 + 0];
        s1 += v * rw[c * 3 + 1];
        s2 += v * rw[c * 3 + 2];
    }
    for (int o = 16; o > 0; o >>= 1) {
        s0 += __shfl_down_sync(0xffffffffu, s0, o);
        s1 += __shfl_down_sync(0xffffffffu, s1, o);
        s2 += __shfl_down_sync(0xffffffffu, s2, o);
    }
    if (lane == 0) {
        float m = fmaxf(s0, fmaxf(s1, s2));
        float p0 = __expf(s0 - m), p1 = __expf(s1 - m), p2 = __expf(s2 - m);
        float tot = p0 + p1 + p2;
        p0 /= tot; p1 /= tot; p2 /= tot;
        int amin = 0; float pm = p0;
        if (p1 <= pm) { amin = 1; pm = p1; }
        if (p2 <= pm) { amin = 2; pm = p2; }
        float denom = (p0 + p1 + p2) - pm;
        g_wfull[t * 3 + 0] = (amin == 0) ? 0.f : p0 / denom;
        g_wfull[t * 3 + 1] = (amin == 1) ? 0.f : p1 / denom;
        g_wfull[t * 3 + 2] = (amin == 2) ? 0.f : p2 / denom;
    }
}

// ---------------------------------------------------------------------------
// Deterministic per-expert compaction
// ---------------------------------------------------------------------------
__global__ void compact_kernel() {
    int e = blockIdx.x;
    int tid = threadIdx.x;
    int lane = tid & 31, wr = tid >> 5;
    __shared__ int sh[32];
    __shared__ int sbase;
    if (tid == 0) sbase = 0;
    __syncthreads();
    for (int start = 0; start < BSn; start += 1024) {
        int t = start + tid;
        float w = (t < BSn) ? g_wfull[t * 3 + e] : 0.f;
        int flag = (w > 0.f) ? 1 : 0;
        int x = flag;
        #pragma unroll
        for (int o = 1; o < 32; o <<= 1) {
            int y = __shfl_up_sync(0xffffffffu, x, o);
            if (lane >= o) x += y;
        }
        if (lane == 31) sh[wr] = x;
        __syncthreads();
        if (wr == 0) {
            int v = sh[lane];
            #pragma unroll
            for (int o = 1; o < 32; o <<= 1) {
                int y = __shfl_up_sync(0xffffffffu, v, o);
                if (lane >= o) v += y;
            }
            sh[lane] = v;
        }
        __syncthreads();
        int warp_excl = wr ? sh[wr - 1] : 0;
        int pos = sbase + warp_excl + (x - flag);
        if (t < BSn) {
            if (flag) {
                g_eidx[e * BSn + pos] = t;
                g_slot[t * 3 + e] = pos;
                g_wslot[e * BSn + pos] = w;
            } else {
                g_slot[t * 3 + e] = -1;
            }
        }
        __syncthreads();
        if (tid == 0) sbase += sh[31];
        __syncthreads();
    }
    if (tid == 0) g_cnt[e] = sbase;
}

// ---------------------------------------------------------------------------
// out += sum_e moe_e (slot-space gather, fixed expert order) transposed
// ---------------------------------------------------------------------------
__global__ void addmoe_tr(float* __restrict__ out) {
    __shared__ float sh[32][33];
    int b = blockIdx.z;
    int s0 = blockIdx.x * 32, c0 = blockIdx.y * 32;
    #pragma unroll
    for (int i = 0; i < 4; i++) {
        int sl = threadIdx.y + i * 8;
        int s = s0 + sl, c = c0 + threadIdx.x;
        if (s < Sn && c < Cc) {
            int t = b * Sn + s;
            float acc = 0.f;
            #pragma unroll
            for (int e = 0; e < En; e++) {
                int slot = g_slot[t * 3 + e];
                if (slot >= 0)
                    acc += g_moeo[((size_t)e * BSn + slot) * Cc + c];
            }
            sh[threadIdx.x][sl] = acc;
        }
    }
    __syncthreads();
    #pragma unroll
    for (int i = 0; i < 4; i++) {
        int cl = threadIdx.y + i * 8;
        int s = s0 + threadIdx.x, c = c0 + cl;
        if (s < Sn && c < Cc) {
            size_t idx = (size_t)b * CS + (size_t)c * Sn + s;
            out[idx] += sh[cl][threadIdx.x];
        }
    }
}

// ---------------------------------------------------------------------------
// Host launcher
// ---------------------------------------------------------------------------
extern "C" void kernel_launch(void* const* d_in, const int* in_sizes, int n_in,
                              void* d_out, int out_size) {
    const float* x        = (const float*)d_in[0];
    const float* ln_w     = (const float*)d_in[1];
    const float* ln_b     = (const float*)d_in[2];
    const float* qkv_w    = (const float*)d_in[3];
    const float* proj_w   = (const float*)d_in[4];
    const float* router_w = (const float*)d_in[5];
    const float* gate_w   = (const float*)d_in[6];
    const float* up_w     = (const float*)d_in[7];
    const float* down_w   = (const float*)d_in[8];
    float* out = (float*)d_out;

    cudaFuncSetAttribute(mma_gemm<false, 0>,
                         cudaFuncAttributeMaxDynamicSharedMemorySize, SMEM_BYTES);
    cudaFuncSetAttribute(mma_gemm<false, 1>,
                         cudaFuncAttributeMaxDynamicSharedMemorySize, SMEM_BYTES);
    cudaFuncSetAttribute(mma_gemm<false, 2>,
                         cudaFuncAttributeMaxDynamicSharedMemorySize, SMEM_BYTES);
    cudaFuncSetAttribute(flash_attn,
                         cudaFuncAttributeMaxDynamicSharedMemorySize, FSMEM_BYTES);

    float *projop, *gp, *moeop, *wslotp;
    __nv_bfloat16 *tokp, *qkvp, *attp, *tok2p, *hidp;
    __nv_bfloat16 *qkvwp, *projwp, *gatewp, *upwp, *downwp;
    int *eidxp, *cntp;
    cudaGetSymbolAddress((void**)&projop,  g_projo);
    cudaGetSymbolAddress((void**)&gp,      g_gbuf);
    cudaGetSymbolAddress((void**)&moeop,   g_moeo);
    cudaGetSymbolAddress((void**)&wslotp,  g_wslot);
    cudaGetSymbolAddress((void**)&tokp,    s_tok);
    cudaGetSymbolAddress((void**)&qkvp,    s_qkv);
    cudaGetSymbolAddress((void**)&attp,    s_att);
    cudaGetSymbolAddress((void**)&tok2p,   s_tok2);
    cudaGetSymbolAddress((void**)&hidp,    s_hid);
    cudaGetSymbolAddress((void**)&qkvwp,   s_qkvw);
    cudaGetSymbolAddress((void**)&projwp,  s_projw);
    cudaGetSymbolAddress((void**)&gatewp,  s_gatew);
    cudaGetSymbolAddress((void**)&upwp,    s_upw);
    cudaGetSymbolAddress((void**)&downwp,  s_downw);
    cudaGetSymbolAddress((void**)&eidxp,   g_eidx);
    cudaGetSymbolAddress((void**)&cntp,    g_cnt);

    dim3 trGrid((Sn + 31) / 32, Cc / 32, Bn);
    dim3 trBlk(32, 8);

    // 0) weight conversions
    convert_split<<<512, 256>>>(qkv_w,  qkvwp,  P_QKVW,  P_QKVW / 4);
    convert_split<<<512, 256>>>(proj_w, projwp, P_PROJW, P_PROJW / 4);
    convert_split<<<512, 256>>>(gate_w, gatewp, P_GATEW, P_GATEW / 4);
    convert_split<<<512, 256>>>(up_w,   upwp,   P_GATEW, P_GATEW / 4);
    convert_split<<<512, 256>>>(down_w, downwp, P_DOWNW, P_DOWNW / 4);

    // 1) LayerNorm -> s_tok planes
    ln_reduce<<<dim3(64, Bn), 256>>>(x);
    ln_finalize<<<Bn, 64>>>();
    ln_apply_tr<<<trGrid, trBlk>>>(x, ln_w, ln_b);

    // 2) QKV -> s_qkv planes
    mma_gemm<false, 1><<<dim3(18, 46, 1), 256, SMEM_BYTES>>>(
        tokp, P_TOK, qkvwp, P_QKVW, qkvp, P_QKV,
        nullptr, nullptr, nullptr, 0, nullptr,
        BSn, C3, Cc, Cc, Cc, C3, C3,
        1, 0, 0, 0, 0, 0, 0);

    // 3) fused attention (QK^T + softmax + PV) -> s_att planes
    flash_attn<<<dim3(6, 64), 256, FSMEM_BYTES>>>();

    // 4) proj -> fp32 g_projo
    mma_gemm<false, 0><<<dim3(6, 46, 1), 256, SMEM_BYTES>>>(
        attp, P_TOK, projwp, P_PROJW, projop, 0,
        nullptr, nullptr, nullptr, 0, nullptr,
        BSn, Cc, Cc, Cc, Cc, Cc, Cc,
        1, 0, 0, 0, 0, 0, 0);

    // 5) x2 = x + po
    addproj_tr<<<trGrid, trBlk>>>(x, out);

    // 6) router + compaction
    router_kernel<<<Sn, 256>>>(router_w);
    compact_kernel<<<En, 1024>>>();

    // 7) gate (fp32 g), then up with fused silu -> s_hid planes
    mma_gemm<false, 0><<<dim3(16, 46, En), 256, SMEM_BYTES>>>(
        tok2p, P_TOK, gatewp, P_GATEW, gp, 0,
        nullptr, nullptr, eidxp, BSn, cntp,
        BSn, HIDn, Cc, Cc, Cc, HIDn, HIDn,
        1, 0, 0, (long long)Cc * HIDn, 0, (long long)BSn * HIDn, 0);
    mma_gemm<false, 2><<<dim3(16, 46, En), 256, SMEM_BYTES>>>(
        tok2p, P_TOK, upwp, P_GATEW, hidp, P_HID,
        gp, wslotp, eidxp, BSn, cntp,
        BSn, HIDn, Cc, Cc, Cc, HIDn, HIDn,
        1, 0, 0, (long long)Cc * HIDn, 0, (long long)BSn * HIDn, 0);

    // 8) down per expert -> g_moeo slot space
    mma_gemm<false, 0><<<dim3(6, 46, En), 256, SMEM_BYTES>>>(
        hidp, P_HID, downwp, P_DOWNW, moeop, 0,
        nullptr, nullptr, nullptr, 0, cntp,
        BSn, Cc, HIDn, HIDn, HIDn, Cc, Cc,
        1, (long long)BSn * HIDn, 0,
        (long long)HIDn * Cc, 0,
        (long long)BSn * Cc, 0);

    // 9) out += sum_e moe_e
    addmoe_tr<<<trGrid, trBlk>>>(out);

    (void)in_sizes; (void)n_in; (void)out_size;
}